// round 1
// baseline (speedup 1.0000x reference)
#include <cuda_runtime.h>
#include <cuda_bf16.h>
#include <cstdint>

// Problem constants
#define BB    64
#define TT    256
#define KK    256      // INPUT_SIZE
#define LBL   51       // L
#define NN    2601     // L*L
#define ESTR  2604     // padded row stride for X (16B-aligned rows)
#define MM    16384    // B*T

// Scratch (device globals: no allocations allowed)
__device__ float g_Wp[KK * NN];          // folded weights: trans_W + broadcast(state_W)
__device__ float g_bp[NN + 8];           // folded bias
__device__ float g_X[(size_t)MM * ESTR]; // exp(mask * energy), row stride ESTR (~170.6 MB)

// ---------------------------------------------------------------------------
// Prep: fold state weights/bias into transition weights/bias
// ---------------------------------------------------------------------------
__global__ void prep_kernel(const float* __restrict__ sW, const float* __restrict__ sb,
                            const float* __restrict__ tW, const float* __restrict__ tb) {
    int idx = blockIdx.x * blockDim.x + threadIdx.x;
    const int total = KK * NN;
    if (idx < total) {
        int n = idx % NN;
        int k = idx / NN;
        g_Wp[idx] = tW[idx] + sW[k * LBL + (n % LBL)];
    }
    if (idx < NN) g_bp[idx] = tb[idx] + sb[idx % LBL];
}

// ---------------------------------------------------------------------------
// GEMM + exp epilogue:  X[m, n] = exp( mask[m] * (A[m,:] . Wp[:,n] + bp[n]) )
// A: [16384, 256] row-major.  Tiles: 128x64, BK=16, 256 threads, 8x4 microtile.
// ---------------------------------------------------------------------------
#define GBM 128
#define GBN 64
#define GBK 16

__global__ __launch_bounds__(256) void gemm_exp_kernel(const float* __restrict__ A,
                                                       const float* __restrict__ mask) {
    __shared__ __align__(16) float As[GBK][GBM + 4]; // transposed: As[k][m]
    __shared__ __align__(16) float Bs[GBK][GBN];

    const int tid = threadIdx.x;
    const int tx = tid & 15;   // n dim (x4)
    const int ty = tid >> 4;   // m dim (x8)
    const int m0 = blockIdx.y * GBM;
    const int n0 = blockIdx.x * GBN;

    float acc[8][4];
#pragma unroll
    for (int i = 0; i < 8; i++)
#pragma unroll
        for (int jj = 0; jj < 4; jj++) acc[i][jj] = 0.f;

    for (int k0 = 0; k0 < KK; k0 += GBK) {
        // Load A tile 128x16 (float4, transposed into As[k][m])
#pragma unroll
        for (int l = 0; l < 2; l++) {
            int idx = tid + l * 256;      // 0..511 over 512 float4s
            int r   = idx >> 2;           // 0..127
            int c4  = idx & 3;            // 0..3
            float4 v = *(const float4*)(A + (size_t)(m0 + r) * KK + k0 + c4 * 4);
            As[c4 * 4 + 0][r] = v.x;
            As[c4 * 4 + 1][r] = v.y;
            As[c4 * 4 + 2][r] = v.z;
            As[c4 * 4 + 3][r] = v.w;
        }
        // Load B tile 16x64 (guard N edge)
#pragma unroll
        for (int l = 0; l < 4; l++) {
            int idx = tid + l * 256;
            int r = idx >> 6;             // 0..15
            int c = idx & 63;
            int n = n0 + c;
            Bs[r][c] = (n < NN) ? g_Wp[(size_t)(k0 + r) * NN + n] : 0.f;
        }
        __syncthreads();

#pragma unroll
        for (int k = 0; k < GBK; k++) {
            float a[8], bb[4];
#pragma unroll
            for (int i = 0; i < 8; i++) a[i] = As[k][ty * 8 + i];
#pragma unroll
            for (int jj = 0; jj < 4; jj++) bb[jj] = Bs[k][tx * 4 + jj];
#pragma unroll
            for (int i = 0; i < 8; i++)
#pragma unroll
                for (int jj = 0; jj < 4; jj++) acc[i][jj] += a[i] * bb[jj];
        }
        __syncthreads();
    }

    // Epilogue: add bias, apply mask, exponentiate, store
#pragma unroll
    for (int i = 0; i < 8; i++) {
        int m = m0 + ty * 8 + i;
        float mk = mask[m];
#pragma unroll
        for (int jj = 0; jj < 4; jj++) {
            int n = n0 + tx * 4 + jj;
            if (n < NN)
                g_X[(size_t)m * ESTR + n] = __expf(mk * (acc[i][jj] + g_bp[n]));
        }
    }
}

// ---------------------------------------------------------------------------
// Forward-algorithm scan. One CTA per batch element, 256 threads = 4 i-groups
// x 64 j-slots. Recurrence in exp-domain:
//   p_new[j] = ref + log( sum_i exp(part[i]-ref) * X[i,j] )
// X prefetched per timestep via cp.async double buffering.
// ---------------------------------------------------------------------------
__device__ __forceinline__ void cp_async16(void* smem, const void* gptr) {
    uint32_t s = (uint32_t)__cvta_generic_to_shared(smem);
    asm volatile("cp.async.cg.shared.global [%0], [%1], 16;\n" :: "r"(s), "l"(gptr));
}

__global__ __launch_bounds__(256) void scan_kernel(const float* __restrict__ mask,
                                                   const int* __restrict__ target,
                                                   float* __restrict__ out) {
    const int b   = blockIdx.x;
    const int tid = threadIdx.x;
    const int j   = tid & 63;
    const int g   = tid >> 6;

    __shared__ float part[LBL];
    __shared__ float sa[LBL];
    __shared__ float red[256];
    __shared__ float scref[1];
    __shared__ float s_tgt[1];
    __shared__ __align__(16) float buf[2][ESTR];

    const float* Xb = g_X + (size_t)b * TT * ESTR;

    // Prefetch t=1 into buf[1]
    {
        const float4* src = (const float4*)(Xb + (size_t)1 * ESTR);
        float4* dst = (float4*)buf[1];
        for (int c = tid; c < ESTR / 4; c += 256) cp_async16(&dst[c], &src[c]);
        asm volatile("cp.async.commit_group;\n" ::: "memory");
    }

    int prev = target[b * TT];
    // t=0 init: part[j] = mask0*energy0[L-1, j] == log X0[L-1, j]
    if (tid < LBL) part[tid] = __logf(Xb[(LBL - 1) * LBL + tid]);
    if (tid == 0)  s_tgt[0]  = __logf(Xb[(LBL - 1) * LBL + prev]);
    __syncthreads();
    {
        float r0 = part[0];
        if (tid < LBL) sa[tid] = __expf(part[tid] - r0);
        if (tid == 0)  scref[0] = r0;
    }
    // (loop-top barrier covers sa/scref visibility)

    for (int t = 1; t < TT; t++) {
        const int cur = t & 1;
        if (t < TT - 1) {
            const float4* src = (const float4*)(Xb + (size_t)(t + 1) * ESTR);
            float4* dst = (float4*)buf[cur ^ 1];
            for (int c = tid; c < ESTR / 4; c += 256) cp_async16(&dst[c], &src[c]);
            asm volatile("cp.async.commit_group;\n" ::: "memory");
            asm volatile("cp.async.wait_group 1;\n" ::: "memory");
        } else {
            asm volatile("cp.async.wait_group 0;\n" ::: "memory");
        }
        __syncthreads();  // (1) buffer + sa + scref ready

        const float m  = mask[b * TT + t];
        const int   tg = target[b * TT + t];
        const float* Xc = buf[cur];

        float s = 0.f;
        if (j < LBL) {
#pragma unroll
            for (int i = g; i < LBL; i += 4) s += sa[i] * Xc[i * LBL + j];
        }
        red[tid] = s;
        if (tid == 255) s_tgt[0] += __logf(Xc[prev * LBL + tg]); // log X == mask*energy
        prev = tg;
        __syncthreads();  // (2) partials ready

        if (g == 0 && j < LBL) {
            float tot = red[j] + red[j + 64] + red[j + 128] + red[j + 192];
            float r   = scref[0];
            float pn  = r + __logf(tot);
            float p   = part[j];
            p += (pn - p) * m;
            part[j] = p;
        }
        __syncthreads();  // (3) part updated

        if (tid < LBL) {
            float r2 = part[0];
            sa[tid] = __expf(part[tid] - r2);
            if (tid == 0) scref[0] = r2;
        }
        // loop-top barrier of next iteration protects these writes
    }

    __syncthreads();
    if (tid == 0) {
        float mx = -1e30f;
        for (int i = 0; i < LBL; i++) mx = fmaxf(mx, part[i]);
        float sm = 0.f;
        for (int i = 0; i < LBL; i++) sm += __expf(part[i] - mx);
        out[b] = mx + __logf(sm) - s_tgt[0];
    }
}

// ---------------------------------------------------------------------------
extern "C" void kernel_launch(void* const* d_in, const int* in_sizes, int n_in,
                              void* d_out, int out_size) {
    const float* input  = (const float*)d_in[0];
    const float* mask   = (const float*)d_in[1];
    const int*   target = (const int*)d_in[2];
    const float* sW     = (const float*)d_in[3];
    const float* sb     = (const float*)d_in[4];
    const float* tW     = (const float*)d_in[5];
    const float* tb     = (const float*)d_in[6];
    float* out = (float*)d_out;

    (void)in_sizes; (void)n_in; (void)out_size;

    const int prep_total = KK * NN;
    prep_kernel<<<(prep_total + 255) / 256, 256>>>(sW, sb, tW, tb);

    dim3 ggrid((NN + GBN - 1) / GBN, MM / GBM);  // (41, 128)
    gemm_exp_kernel<<<ggrid, 256>>>(input, mask);

    scan_kernel<<<BB, 256>>>(mask, target, out);
}

// round 3
// speedup vs baseline: 2.1740x; 2.1740x over previous
#include <cuda_runtime.h>
#include <cuda_bf16.h>
#include <cstdint>

// Problem constants
#define BB    64
#define TT    256
#define KK    256      // INPUT_SIZE
#define LBL   51       // L
#define NN    2601     // L*L
#define NPAD  2688     // 21 * 128
#define ESTR  2688     // X row stride (bf16 elems) = 5376 B
#define MM    16384    // B*T

// ---------------------------------------------------------------------------
// Device globals (no allocations allowed)
// ---------------------------------------------------------------------------
__device__ __align__(256) __nv_bfloat16 g_Abf[MM * KK];          // input, bf16
__device__ __align__(256) __nv_bfloat16 g_Wpb[NPAD * KK];        // folded W, [n][k] bf16
__device__ __align__(256) float         g_bp[NPAD];              // folded bias
__device__ __align__(256) __nv_bfloat16 g_X[(size_t)MM * ESTR];  // exp(mask*energy) (~88MB)

// ---------------------------------------------------------------------------
// Helpers (family-portable PTX only: cp.async, ldmatrix, mma.sync)
// ---------------------------------------------------------------------------
__device__ __forceinline__ uint32_t smem_u32(const void* p) {
    uint32_t a;
    asm("{ .reg .u64 t; cvta.to.shared.u64 t, %1; cvt.u32.u64 %0, t; }" : "=r"(a) : "l"(p));
    return a;
}
__device__ __forceinline__ void cp_async16(uint32_t smem, const void* g) {
    asm volatile("cp.async.cg.shared.global [%0], [%1], 16;\n" :: "r"(smem), "l"(g));
}
#define CP_COMMIT() asm volatile("cp.async.commit_group;\n" ::: "memory")
#define CP_WAIT(n)  asm volatile("cp.async.wait_group %0;\n" :: "n"(n) : "memory")

#define LDSM4(r0, r1, r2, r3, addr) \
    asm volatile("ldmatrix.sync.aligned.m8n8.x4.shared.b16 {%0,%1,%2,%3}, [%4];\n" \
                 : "=r"(r0), "=r"(r1), "=r"(r2), "=r"(r3) : "r"(addr))

#define MMA16816(c, a, b) \
    asm volatile("mma.sync.aligned.m16n8k16.row.col.f32.bf16.bf16.f32 " \
                 "{%0,%1,%2,%3}, {%4,%5,%6,%7}, {%8,%9}, {%0,%1,%2,%3};\n" \
                 : "+f"((c)[0]), "+f"((c)[1]), "+f"((c)[2]), "+f"((c)[3]) \
                 : "r"((a)[0]), "r"((a)[1]), "r"((a)[2]), "r"((a)[3]), \
                   "r"((b)[0]), "r"((b)[1]))

// ---------------------------------------------------------------------------
// Prep kernels
// ---------------------------------------------------------------------------
__global__ void prep_w_kernel(const float* __restrict__ sW, const float* __restrict__ sb,
                              const float* __restrict__ tW, const float* __restrict__ tb) {
    int n = blockIdx.x * blockDim.x + threadIdx.x;
    if (n >= NPAD) return;
    if (n < NN) {
        g_bp[n] = tb[n] + sb[n % LBL];
        int col = n % LBL;
#pragma unroll 1
        for (int kb = 0; kb < KK / 8; kb++) {
            __nv_bfloat162 p[4];
#pragma unroll
            for (int i = 0; i < 4; i++) {
                int k0 = kb * 8 + 2 * i;
                float v0 = tW[(size_t)k0 * NN + n] + sW[k0 * LBL + col];
                float v1 = tW[(size_t)(k0 + 1) * NN + n] + sW[(k0 + 1) * LBL + col];
                p[i] = __floats2bfloat162_rn(v0, v1);
            }
            *(uint4*)&g_Wpb[n * KK + kb * 8] = *(uint4*)p;
        }
    } else {
        g_bp[n] = 0.f;
        for (int kb = 0; kb < KK / 8; kb++) {
            uint4 z = {0, 0, 0, 0};
            *(uint4*)&g_Wpb[n * KK + kb * 8] = z;
        }
    }
}

__global__ void prep_a_kernel(const float* __restrict__ A) {
    int idx = blockIdx.x * blockDim.x + threadIdx.x;  // over MM*KK/4
    if (idx >= MM * KK / 4) return;
    float4 v = *(const float4*)(A + (size_t)idx * 4);
    __nv_bfloat162 p0 = __floats2bfloat162_rn(v.x, v.y);
    __nv_bfloat162 p1 = __floats2bfloat162_rn(v.z, v.w);
    uint2 o;
    o.x = *(uint32_t*)&p0;
    o.y = *(uint32_t*)&p1;
    *(uint2*)&g_Abf[(size_t)idx * 4] = o;
}

// ---------------------------------------------------------------------------
// mma.sync GEMM + exp epilogue:
//   X[m, n] = bf16( exp( mask[m] * (A . Wp + bp) ) )
// CTA tile 128x128, K-step 32, double-buffered cp.async.
// 8 warps: wm = wid>>2 (2), wn = wid&3 (4); warp tile 64(m) x 32(n).
// ---------------------------------------------------------------------------
#define STG_ELEMS 136   // epilogue stage row stride in bf16 (272 B)

__global__ __launch_bounds__(256, 2) void gemm_exp_kernel(const float* __restrict__ mask) {
    // Mainloop: 2 stages x (A 8KB + B 8KB). Epilogue stage: 128*272B = 34816B.
    __shared__ __align__(128) char sm[36864];

    const int tid = threadIdx.x;
    const int l   = tid & 31;
    const int wid = tid >> 5;
    const int wm  = wid >> 2;   // 0..1
    const int wn  = wid & 3;    // 0..3
    const int m0  = blockIdx.y * 128;
    const int n0  = blockIdx.x * 128;

    const uint32_t smBase = smem_u32(sm);

    // ldmatrix source offsets (swizzled): row*64 + ((seg ^ (row&3))<<4)
    // A: per m-tile i and k16 sub-step
    const int a_r = (l & 7) + 8 * ((l >> 3) & 1);
    const int a_s = (l >> 4);
    uint32_t a_off[4][2];
#pragma unroll
    for (int i = 0; i < 4; i++)
#pragma unroll
        for (int ks16 = 0; ks16 < 2; ks16++) {
            int r = wm * 64 + 16 * i + a_r;
            int seg = ks16 * 2 + a_s;
            a_off[i][ks16] = r * 64 + ((seg ^ (r & 3)) << 4);
        }
    // B: per n-tile-pair jj and k16
    const int b_r = (l & 7) + 8 * ((l >> 4) & 1);
    const int b_s = (l >> 3) & 1;
    uint32_t b_off[2][2];
#pragma unroll
    for (int jj = 0; jj < 2; jj++)
#pragma unroll
        for (int ks16 = 0; ks16 < 2; ks16++) {
            int r = wn * 32 + 16 * jj + b_r;
            int seg = ks16 * 2 + b_s;
            b_off[jj][ks16] = r * 64 + ((seg ^ (r & 3)) << 4);
        }

    // cp.async chunk coords (2 chunks per thread per operand)
    const int c0r = tid >> 2, c0s = tid & 3;           // chunk tid
    const int c1r = (tid + 256) >> 2, c1s = tid & 3;   // chunk tid+256
    const uint32_t so0 = c0r * 64 + ((c0s ^ (c0r & 3)) << 4);
    const uint32_t so1 = c1r * 64 + ((c1s ^ (c1r & 3)) << 4);

#define LOAD_STAGE(s, ks) do {                                                        \
        uint32_t bA = smBase + (s) * 16384;                                           \
        uint32_t bW = bA + 8192;                                                      \
        cp_async16(bA + so0, g_Abf + (size_t)(m0 + c0r) * KK + (ks) * 32 + c0s * 8);  \
        cp_async16(bA + so1, g_Abf + (size_t)(m0 + c1r) * KK + (ks) * 32 + c1s * 8);  \
        cp_async16(bW + so0, g_Wpb + (size_t)(n0 + c0r) * KK + (ks) * 32 + c0s * 8);  \
        cp_async16(bW + so1, g_Wpb + (size_t)(n0 + c1r) * KK + (ks) * 32 + c1s * 8);  \
        CP_COMMIT();                                                                  \
    } while (0)

    float acc[4][4][4];
#pragma unroll
    for (int i = 0; i < 4; i++)
#pragma unroll
        for (int j = 0; j < 4; j++)
#pragma unroll
            for (int q = 0; q < 4; q++) acc[i][j][q] = 0.f;

    LOAD_STAGE(0, 0);

#pragma unroll 1
    for (int ks = 0; ks < 8; ks++) {
        if (ks < 7) {
            LOAD_STAGE((ks + 1) & 1, ks + 1);
            CP_WAIT(1);
        } else {
            CP_WAIT(0);
        }
        __syncthreads();

        const uint32_t bA = smBase + (ks & 1) * 16384;
        const uint32_t bW = bA + 8192;

#pragma unroll
        for (int ks16 = 0; ks16 < 2; ks16++) {
            uint32_t a[4][4];
            uint32_t b[4][2];
#pragma unroll
            for (int i = 0; i < 4; i++)
                LDSM4(a[i][0], a[i][1], a[i][2], a[i][3], bA + a_off[i][ks16]);
#pragma unroll
            for (int jj = 0; jj < 2; jj++)
                LDSM4(b[2 * jj][0], b[2 * jj][1], b[2 * jj + 1][0], b[2 * jj + 1][1],
                      bW + b_off[jj][ks16]);
#pragma unroll
            for (int i = 0; i < 4; i++)
#pragma unroll
                for (int j = 0; j < 4; j++)
                    MMA16816(acc[i][j], a[i], b[j]);
        }
        __syncthreads();
    }

    // -----------------------------------------------------------------------
    // Epilogue: exp(mask*(acc+bias)) -> bf16, stage via smem, coalesced write
    // acc[i][j]: c0 (m=16i+l/4, n=8j+2(l&3)), c1 (n+1), c2 (m+8), c3 (m+8,n+1)
    // -----------------------------------------------------------------------
    __nv_bfloat16* stage = (__nv_bfloat16*)sm;
    const int qr = l >> 2, qc = l & 3;

    float bj0[4], bj1[4];
#pragma unroll
    for (int j = 0; j < 4; j++) {
        int n = n0 + wn * 32 + 8 * j + 2 * qc;
        bj0[j] = g_bp[n];
        bj1[j] = g_bp[n + 1];
    }

#pragma unroll
    for (int i = 0; i < 4; i++) {
        int mlo = wm * 64 + 16 * i + qr;
        float mk_lo = mask[m0 + mlo];
        float mk_hi = mask[m0 + mlo + 8];
#pragma unroll
        for (int j = 0; j < 4; j++) {
            int nl = wn * 32 + 8 * j + 2 * qc;
            float f00 = __expf(mk_lo * (acc[i][j][0] + bj0[j]));
            float f01 = __expf(mk_lo * (acc[i][j][1] + bj1[j]));
            float f10 = __expf(mk_hi * (acc[i][j][2] + bj0[j]));
            float f11 = __expf(mk_hi * (acc[i][j][3] + bj1[j]));
            *(__nv_bfloat162*)&stage[mlo * STG_ELEMS + nl]       = __floats2bfloat162_rn(f00, f01);
            *(__nv_bfloat162*)&stage[(mlo + 8) * STG_ELEMS + nl] = __floats2bfloat162_rn(f10, f11);
        }
    }
    __syncthreads();

    // Copy out: 128 rows x 16 chunks(16B); 8 chunks per thread
#pragma unroll
    for (int h = 0; h < 8; h++) {
        int c = tid + h * 256;
        int row = c >> 4;
        int seg = c & 15;
        uint4 v = *(const uint4*)&stage[row * STG_ELEMS + seg * 8];
        *(uint4*)&g_X[(size_t)(m0 + row) * ESTR + n0 + seg * 8] = v;
    }
}

// ---------------------------------------------------------------------------
// Forward-algorithm scan (bf16 X). One CTA per batch element.
//   p_new[j] = ref + log( sum_i exp(part[i]-ref) * X[i,j] )
// ---------------------------------------------------------------------------
__global__ __launch_bounds__(256) void scan_kernel(const float* __restrict__ mask,
                                                   const int* __restrict__ target,
                                                   float* __restrict__ out) {
    const int b   = blockIdx.x;
    const int tid = threadIdx.x;
    const int j   = tid & 63;
    const int g   = tid >> 6;

    __shared__ float part[LBL];
    __shared__ float sa[LBL];
    __shared__ float red[256];
    __shared__ float scref[1];
    __shared__ float s_tgt[1];
    __shared__ __align__(16) __nv_bfloat16 buf[2][ESTR];

    const __nv_bfloat16* Xb = g_X + (size_t)b * TT * ESTR;
    const int CH = ESTR * 2 / 16;  // 336 16B-chunks per row

    // Prefetch t=1 into buf[1]
    {
        const char* src = (const char*)(Xb + (size_t)1 * ESTR);
        uint32_t dst = smem_u32(buf[1]);
        for (int c = tid; c < CH; c += 256) cp_async16(dst + c * 16, src + c * 16);
        CP_COMMIT();
    }

    int prev = target[b * TT];
    if (tid < LBL) part[tid] = __logf(__bfloat162float(Xb[(LBL - 1) * LBL + tid]));
    if (tid == 0)  s_tgt[0]  = __logf(__bfloat162float(Xb[(LBL - 1) * LBL + prev]));
    __syncthreads();
    {
        float r0 = part[0];
        if (tid < LBL) sa[tid] = __expf(part[tid] - r0);
        if (tid == 0)  scref[0] = r0;
    }
    // (loop-top barrier covers sa/scref visibility)

    for (int t = 1; t < TT; t++) {
        const int cur = t & 1;
        if (t < TT - 1) {
            const char* src = (const char*)(Xb + (size_t)(t + 1) * ESTR);
            uint32_t dst = smem_u32(buf[cur ^ 1]);
            for (int c = tid; c < CH; c += 256) cp_async16(dst + c * 16, src + c * 16);
            CP_COMMIT();
            CP_WAIT(1);
        } else {
            CP_WAIT(0);
        }
        __syncthreads();  // (1) buffer + sa + scref ready

        const float m  = mask[b * TT + t];
        const int   tg = target[b * TT + t];
        const __nv_bfloat16* Xc = buf[cur];

        float s = 0.f;
        if (j < LBL) {
#pragma unroll
            for (int i = g; i < LBL; i += 4)
                s += sa[i] * __bfloat162float(Xc[i * LBL + j]);
        }
        red[tid] = s;
        if (tid == 255) s_tgt[0] += __logf(__bfloat162float(Xc[prev * LBL + tg]));
        prev = tg;
        __syncthreads();  // (2) partials ready

        if (g == 0 && j < LBL) {
            float tot = red[j] + red[j + 64] + red[j + 128] + red[j + 192];
            float r   = scref[0];
            float pn  = r + __logf(tot);
            float p   = part[j];
            p += (pn - p) * m;
            part[j] = p;
        }
        __syncthreads();  // (3) part updated

        if (tid < LBL) {
            float r2 = part[0];
            sa[tid] = __expf(part[tid] - r2);
            if (tid == 0) scref[0] = r2;
        }
        // loop-top barrier of next iteration protects these writes
    }

    __syncthreads();
    if (tid == 0) {
        float mx = -1e30f;
        for (int i = 0; i < LBL; i++) mx = fmaxf(mx, part[i]);
        float sm = 0.f;
        for (int i = 0; i < LBL; i++) sm += __expf(part[i] - mx);
        out[b] = mx + __logf(sm) - s_tgt[0];
    }
}

// ---------------------------------------------------------------------------
extern "C" void kernel_launch(void* const* d_in, const int* in_sizes, int n_in,
                              void* d_out, int out_size) {
    const float* input  = (const float*)d_in[0];
    const float* mask   = (const float*)d_in[1];
    const int*   target = (const int*)d_in[2];
    const float* sW     = (const float*)d_in[3];
    const float* sb     = (const float*)d_in[4];
    const float* tW     = (const float*)d_in[5];
    const float* tb     = (const float*)d_in[6];
    float* out = (float*)d_out;

    (void)in_sizes; (void)n_in; (void)out_size;

    prep_w_kernel<<<(NPAD + 127) / 128, 128>>>(sW, sb, tW, tb);
    prep_a_kernel<<<(MM * KK / 4 + 255) / 256, 256>>>(input);

    dim3 ggrid(NPAD / 128, MM / 128);  // (21, 128)
    gemm_exp_kernel<<<ggrid, 256>>>(mask);

    scan_kernel<<<BB, 256>>>(mask, target, out);
}

// round 5
// speedup vs baseline: 2.3776x; 1.0937x over previous
#include <cuda_runtime.h>
#include <cuda_bf16.h>
#include <cstdint>

// Problem constants
#define BB    64
#define TT    256
#define KK    256      // INPUT_SIZE
#define LBL   51       // L
#define NN    2601     // L*L
#define NPAD  2688     // 21 * 128
#define ESTR  2688     // X row stride (bf16 elems) = 5376 B
#define MM    16384    // B*T

// ---------------------------------------------------------------------------
// Device globals (no allocations allowed)
// ---------------------------------------------------------------------------
__device__ __align__(256) __nv_bfloat16 g_Abf[MM * KK];          // input, bf16
__device__ __align__(256) __nv_bfloat16 g_Wpb[NPAD * KK];        // folded W, [n][k] bf16
__device__ __align__(256) float         g_bp[NPAD];              // folded bias
__device__ __align__(256) __nv_bfloat16 g_X[(size_t)MM * ESTR];  // exp(mask*energy) (~88MB)

// ---------------------------------------------------------------------------
// Helpers (family-portable PTX only: cp.async, ldmatrix, mma.sync)
// ---------------------------------------------------------------------------
__device__ __forceinline__ uint32_t smem_u32(const void* p) {
    uint32_t a;
    asm("{ .reg .u64 t; cvta.to.shared.u64 t, %1; cvt.u32.u64 %0, t; }" : "=r"(a) : "l"(p));
    return a;
}
__device__ __forceinline__ void cp_async16(uint32_t smem, const void* g) {
    asm volatile("cp.async.cg.shared.global [%0], [%1], 16;\n" :: "r"(smem), "l"(g));
}
#define CP_COMMIT() asm volatile("cp.async.commit_group;\n" ::: "memory")
#define CP_WAIT(n)  asm volatile("cp.async.wait_group %0;\n" :: "n"(n) : "memory")

#define LDSM4(r0, r1, r2, r3, addr) \
    asm volatile("ldmatrix.sync.aligned.m8n8.x4.shared.b16 {%0,%1,%2,%3}, [%4];\n" \
                 : "=r"(r0), "=r"(r1), "=r"(r2), "=r"(r3) : "r"(addr))

#define MMA16816(c, a, b) \
    asm volatile("mma.sync.aligned.m16n8k16.row.col.f32.bf16.bf16.f32 " \
                 "{%0,%1,%2,%3}, {%4,%5,%6,%7}, {%8,%9}, {%0,%1,%2,%3};\n" \
                 : "+f"((c)[0]), "+f"((c)[1]), "+f"((c)[2]), "+f"((c)[3]) \
                 : "r"((a)[0]), "r"((a)[1]), "r"((a)[2]), "r"((a)[3]), \
                   "r"((b)[0]), "r"((b)[1]))

// ---------------------------------------------------------------------------
// Prep kernels
// ---------------------------------------------------------------------------
__global__ void prep_w_kernel(const float* __restrict__ sW, const float* __restrict__ sb,
                              const float* __restrict__ tW, const float* __restrict__ tb) {
    int n = blockIdx.x * blockDim.x + threadIdx.x;
    if (n >= NPAD) return;
    if (n < NN) {
        g_bp[n] = tb[n] + sb[n % LBL];
        int col = n % LBL;
#pragma unroll 1
        for (int kb = 0; kb < KK / 8; kb++) {
            __nv_bfloat162 p[4];
#pragma unroll
            for (int i = 0; i < 4; i++) {
                int k0 = kb * 8 + 2 * i;
                float v0 = tW[(size_t)k0 * NN + n] + sW[k0 * LBL + col];
                float v1 = tW[(size_t)(k0 + 1) * NN + n] + sW[(k0 + 1) * LBL + col];
                p[i] = __floats2bfloat162_rn(v0, v1);
            }
            *(uint4*)&g_Wpb[n * KK + kb * 8] = *(uint4*)p;
        }
    } else {
        g_bp[n] = 0.f;
        for (int kb = 0; kb < KK / 8; kb++) {
            uint4 z = {0, 0, 0, 0};
            *(uint4*)&g_Wpb[n * KK + kb * 8] = z;
        }
    }
}

__global__ void prep_a_kernel(const float* __restrict__ A) {
    int idx = blockIdx.x * blockDim.x + threadIdx.x;  // over MM*KK/4
    if (idx >= MM * KK / 4) return;
    float4 v = *(const float4*)(A + (size_t)idx * 4);
    __nv_bfloat162 p0 = __floats2bfloat162_rn(v.x, v.y);
    __nv_bfloat162 p1 = __floats2bfloat162_rn(v.z, v.w);
    uint2 o;
    o.x = *(uint32_t*)&p0;
    o.y = *(uint32_t*)&p1;
    *(uint2*)&g_Abf[(size_t)idx * 4] = o;
}

// ---------------------------------------------------------------------------
// mma.sync GEMM + exp epilogue (3-stage cp.async pipeline, 1 bar per k-step)
//   X[m, n] = bf16( exp( mask[m] * (A . Wp + bp) ) )
// CTA tile 128x128, K-step 32. 8 warps: warp tile 64(m) x 32(n).
// ---------------------------------------------------------------------------
#define STG_ELEMS 136   // epilogue stage row stride in bf16 (272 B)

__global__ __launch_bounds__(256, 2) void gemm_exp_kernel(const float* __restrict__ mask) {
    // Mainloop: 3 stages x (A 8KB + B 8KB) = 49152B. Epilogue stage 34816B reuses.
    __shared__ __align__(128) char sm[49152];

    const int tid = threadIdx.x;
    const int l   = tid & 31;
    const int wid = tid >> 5;
    const int wm  = wid >> 2;   // 0..1
    const int wn  = wid & 3;    // 0..3
    const int m0  = blockIdx.y * 128;
    const int n0  = blockIdx.x * 128;

    const uint32_t smBase = smem_u32(sm);

    // ldmatrix source offsets (swizzled): row*64 + ((seg ^ (row&3))<<4)
    const int a_r = (l & 7) + 8 * ((l >> 3) & 1);
    const int a_s = (l >> 4);
    uint32_t a_off[4][2];
#pragma unroll
    for (int i = 0; i < 4; i++)
#pragma unroll
        for (int ks16 = 0; ks16 < 2; ks16++) {
            int r = wm * 64 + 16 * i + a_r;
            int seg = ks16 * 2 + a_s;
            a_off[i][ks16] = r * 64 + ((seg ^ (r & 3)) << 4);
        }
    const int b_r = (l & 7) + 8 * ((l >> 4) & 1);
    const int b_s = (l >> 3) & 1;
    uint32_t b_off[2][2];
#pragma unroll
    for (int jj = 0; jj < 2; jj++)
#pragma unroll
        for (int ks16 = 0; ks16 < 2; ks16++) {
            int r = wn * 32 + 16 * jj + b_r;
            int seg = ks16 * 2 + b_s;
            b_off[jj][ks16] = r * 64 + ((seg ^ (r & 3)) << 4);
        }

    // cp.async chunk coords (2 chunks per thread per operand)
    const int c0r = tid >> 2, c0s = tid & 3;
    const int c1r = (tid + 256) >> 2, c1s = tid & 3;
    const uint32_t so0 = c0r * 64 + ((c0s ^ (c0r & 3)) << 4);
    const uint32_t so1 = c1r * 64 + ((c1s ^ (c1r & 3)) << 4);

#define LOAD_STAGE(s, ks) do {                                                        \
        uint32_t bA = smBase + (s) * 16384;                                           \
        uint32_t bW = bA + 8192;                                                      \
        cp_async16(bA + so0, g_Abf + (size_t)(m0 + c0r) * KK + (ks) * 32 + c0s * 8);  \
        cp_async16(bA + so1, g_Abf + (size_t)(m0 + c1r) * KK + (ks) * 32 + c1s * 8);  \
        cp_async16(bW + so0, g_Wpb + (size_t)(n0 + c0r) * KK + (ks) * 32 + c0s * 8);  \
        cp_async16(bW + so1, g_Wpb + (size_t)(n0 + c1r) * KK + (ks) * 32 + c1s * 8);  \
        CP_COMMIT();                                                                  \
    } while (0)

    float acc[4][4][4];
#pragma unroll
    for (int i = 0; i < 4; i++)
#pragma unroll
        for (int j = 0; j < 4; j++)
#pragma unroll
            for (int q = 0; q < 4; q++) acc[i][j][q] = 0.f;

    LOAD_STAGE(0, 0);
    LOAD_STAGE(1, 1);

#pragma unroll 1
    for (int ks = 0; ks < 8; ks++) {
        if (ks < 7) { CP_WAIT(1); } else { CP_WAIT(0); }
        __syncthreads();                      // stage ks%3 ready, prior readers done
        if (ks + 2 < 8) LOAD_STAGE((ks + 2) % 3, ks + 2);

        const uint32_t bA = smBase + (ks % 3) * 16384;
        const uint32_t bW = bA + 8192;

#pragma unroll
        for (int ks16 = 0; ks16 < 2; ks16++) {
            uint32_t a[4][4];
            uint32_t b[4][2];
#pragma unroll
            for (int i = 0; i < 4; i++)
                LDSM4(a[i][0], a[i][1], a[i][2], a[i][3], bA + a_off[i][ks16]);
#pragma unroll
            for (int jj = 0; jj < 2; jj++)
                LDSM4(b[2 * jj][0], b[2 * jj][1], b[2 * jj + 1][0], b[2 * jj + 1][1],
                      bW + b_off[jj][ks16]);
#pragma unroll
            for (int i = 0; i < 4; i++)
#pragma unroll
                for (int j = 0; j < 4; j++)
                    MMA16816(acc[i][j], a[i], b[j]);
        }
        // no trailing barrier: next iteration's bar (after wait) protects stages
    }
    __syncthreads();  // all reads of mainloop stages complete before epilogue reuse

    // Epilogue: exp(mask*(acc+bias)) -> bf16, stage via smem, coalesced write
    __nv_bfloat16* stage = (__nv_bfloat16*)sm;
    const int qr = l >> 2, qc = l & 3;

    float bj0[4], bj1[4];
#pragma unroll
    for (int j = 0; j < 4; j++) {
        int n = n0 + wn * 32 + 8 * j + 2 * qc;
        bj0[j] = g_bp[n];
        bj1[j] = g_bp[n + 1];
    }

#pragma unroll
    for (int i = 0; i < 4; i++) {
        int mlo = wm * 64 + 16 * i + qr;
        float mk_lo = mask[m0 + mlo];
        float mk_hi = mask[m0 + mlo + 8];
#pragma unroll
        for (int j = 0; j < 4; j++) {
            int nl = wn * 32 + 8 * j + 2 * qc;
            float f00 = __expf(mk_lo * (acc[i][j][0] + bj0[j]));
            float f01 = __expf(mk_lo * (acc[i][j][1] + bj1[j]));
            float f10 = __expf(mk_hi * (acc[i][j][2] + bj0[j]));
            float f11 = __expf(mk_hi * (acc[i][j][3] + bj1[j]));
            *(__nv_bfloat162*)&stage[mlo * STG_ELEMS + nl]       = __floats2bfloat162_rn(f00, f01);
            *(__nv_bfloat162*)&stage[(mlo + 8) * STG_ELEMS + nl] = __floats2bfloat162_rn(f10, f11);
        }
    }
    __syncthreads();

#pragma unroll
    for (int h = 0; h < 8; h++) {
        int c = tid + h * 256;
        int row = c >> 4;
        int seg = c & 15;
        uint4 v = *(const uint4*)&stage[row * STG_ELEMS + seg * 8];
        *(uint4*)&g_X[(size_t)(m0 + row) * ESTR + n0 + seg * 8] = v;
    }
}

// ---------------------------------------------------------------------------
// Forward-algorithm scan (bf16 X). One CTA per batch element, 256 threads.
// 6-buffer lead-5 cp.async prefetch (warps 1-7); partition update entirely in
// warp 0 registers (2 barriers per step).
//   p_new[j] = ref + log( sum_i exp(part[i]-ref) * X[i,j] )
// ---------------------------------------------------------------------------
#define SCAN_CH 326   // 16B chunks covering NN*2 = 5202 bytes (326*16 = 5216 <= 5376)

__global__ __launch_bounds__(256) void scan_kernel(const float* __restrict__ mask,
                                                   const int* __restrict__ target,
                                                   float* __restrict__ out) {
    const int b    = blockIdx.x;
    const int tid  = threadIdx.x;
    const int j    = tid & 63;
    const int g    = tid >> 6;
    const int lane = tid & 31;
    const int wid  = tid >> 5;

    __shared__ float sa[64];
    __shared__ float red[256];
    __shared__ float s_mask[TT];
    __shared__ int   s_tg[TT];
    __shared__ float s_tgtE[1];
    __shared__ __align__(16) __nv_bfloat16 buf[6][ESTR];  // 6 * 5376B = 32256B

    const __nv_bfloat16* Xb = g_X + (size_t)b * TT * ESTR;

    // Preload mask/target rows
    s_mask[tid] = mask[b * TT + tid];
    s_tg[tid]   = target[b * TT + tid];

    // Prefetch rows 1..5 (one group each), warps 1-7 only
    if (wid > 0) {
        const int c0 = tid - 32;  // 0..223
#pragma unroll 1
        for (int r = 1; r <= 5; r++) {
            const char* src = (const char*)(Xb + (size_t)r * ESTR);
            uint32_t dst = smem_u32(buf[r]);
            for (int c = c0; c < SCAN_CH; c += 224) cp_async16(dst + c * 16, src + c * 16);
            CP_COMMIT();
        }
    }

    __syncthreads();  // s_tg/s_mask visible to all (fixes the t=0 race)

    // t=0 init: part in warp-0 registers (p0: j=lane, p1: j=lane+32)
    float p0 = -1e30f, p1 = -1e30f, rr = 0.f, tgtE_reg = 0.f;
    if (wid == 0) {
        if (lane < LBL)
            p0 = __logf(__bfloat162float(Xb[(LBL - 1) * LBL + lane]));
        if (lane + 32 < LBL)
            p1 = __logf(__bfloat162float(Xb[(LBL - 1) * LBL + lane + 32]));
        rr = __shfl_sync(0xffffffffu, p0, 0);
        if (lane < LBL)      sa[lane]      = __expf(p0 - rr);
        if (lane + 32 < LBL) sa[lane + 32] = __expf(p1 - rr);
    }
    if (tid == 255)
        tgtE_reg = __logf(__bfloat162float(Xb[(LBL - 1) * LBL + s_tg[0]]));
    // (sa visibility guaranteed by the first loop barrier)

#pragma unroll 1
    for (int t = 1; t < TT; t++) {
        if (wid > 0) {
            // Issue prefetch for row t+5 (clamped; constant group cadence)
            const int tf = (t + 5 < TT) ? (t + 5) : (TT - 1);
            const char* src = (const char*)(Xb + (size_t)tf * ESTR);
            uint32_t dst = smem_u32(buf[(t + 5) % 6]);
            const int c0 = tid - 32;
            for (int c = c0; c < SCAN_CH; c += 224) cp_async16(dst + c * 16, src + c * 16);
            CP_COMMIT();
            CP_WAIT(5);   // row t (issued 5 groups ago) complete
        }
        __syncthreads();  // (1) buf[t%6] ready; sa from previous step visible

        const __nv_bfloat16* Xc = buf[t % 6];

        float s = 0.f, s2 = 0.f;
        if (j < LBL) {
#pragma unroll
            for (int it = 0; it < 13; it++) {
                int i = g + 4 * it;
                if (i < LBL) {
                    float v = sa[i] * __bfloat162float(Xc[i * LBL + j]);
                    if (it & 1) s2 += v; else s += v;
                }
            }
            s += s2;
        }
        red[tid] = s;
        if (tid == 255)
            tgtE_reg += __logf(__bfloat162float(Xc[s_tg[t - 1] * LBL + s_tg[t]]));
        __syncthreads();  // (2) partials ready

        if (wid == 0) {
            const float m = s_mask[t];
            if (lane < LBL) {
                float tot = red[lane] + red[lane + 64] + red[lane + 128] + red[lane + 192];
                float pn  = rr + __logf(tot);
                p0 += (pn - p0) * m;
            }
            if (lane + 32 < LBL) {
                float tot = red[lane + 32] + red[lane + 96] + red[lane + 160] + red[lane + 224];
                float pn  = rr + __logf(tot);
                p1 += (pn - p1) * m;
            }
            rr = __shfl_sync(0xffffffffu, p0, 0);
            if (lane < LBL)      sa[lane]      = __expf(p0 - rr);
            if (lane + 32 < LBL) sa[lane + 32] = __expf(p1 - rr);
        }
        // next iteration's barrier (1) protects sa
    }

    if (tid == 255) s_tgtE[0] = tgtE_reg;
    __syncthreads();

    if (wid == 0) {
        // logsumexp over part (p0 lanes<51, p1 lanes<19)
        float mx = fmaxf(p0, p1);
#pragma unroll
        for (int o = 16; o > 0; o >>= 1)
            mx = fmaxf(mx, __shfl_xor_sync(0xffffffffu, mx, o));
        float sm = 0.f;
        if (lane < LBL)      sm += __expf(p0 - mx);
        if (lane + 32 < LBL) sm += __expf(p1 - mx);
#pragma unroll
        for (int o = 16; o > 0; o >>= 1)
            sm += __shfl_xor_sync(0xffffffffu, sm, o);
        if (lane == 0) out[b] = mx + __logf(sm) - s_tgtE[0];
    }
}

// ---------------------------------------------------------------------------
extern "C" void kernel_launch(void* const* d_in, const int* in_sizes, int n_in,
                              void* d_out, int out_size) {
    const float* input  = (const float*)d_in[0];
    const float* mask   = (const float*)d_in[1];
    const int*   target = (const int*)d_in[2];
    const float* sW     = (const float*)d_in[3];
    const float* sb     = (const float*)d_in[4];
    const float* tW     = (const float*)d_in[5];
    const float* tb     = (const float*)d_in[6];
    float* out = (float*)d_out;

    (void)in_sizes; (void)n_in; (void)out_size;

    prep_w_kernel<<<(NPAD + 127) / 128, 128>>>(sW, sb, tW, tb);
    prep_a_kernel<<<(MM * KK / 4 + 255) / 256, 256>>>(input);

    dim3 ggrid(NPAD / 128, MM / 128);  // (21, 128)
    gemm_exp_kernel<<<ggrid, 256>>>(mask);

    scan_kernel<<<BB, 256>>>(mask, target, out);
}

// round 6
// speedup vs baseline: 2.4971x; 1.0503x over previous
#include <cuda_runtime.h>
#include <cuda_bf16.h>
#include <cstdint>

// Problem constants
#define BB    64
#define TT    256
#define KK    256      // INPUT_SIZE
#define LBL   51       // L
#define NN    2601     // L*L
#define NPAD  2688     // 21 * 128
#define ESTR  2688     // X row stride (bf16 elems) = 5376 B
#define MM    16384    // B*T

// ---------------------------------------------------------------------------
// Device globals (no allocations allowed)
// ---------------------------------------------------------------------------
__device__ __align__(256) __nv_bfloat16 g_Abf[MM * KK];          // input, bf16
__device__ __align__(256) __nv_bfloat16 g_Wpb[NPAD * KK];        // folded W, [n][k] bf16
__device__ __align__(256) float         g_bp[NPAD];              // folded bias
__device__ __align__(256) __nv_bfloat16 g_X[(size_t)MM * ESTR];  // exp(mask*energy) (~88MB)

// ---------------------------------------------------------------------------
// Helpers (family-portable PTX only: cp.async, ldmatrix, mma.sync)
// ---------------------------------------------------------------------------
__device__ __forceinline__ uint32_t smem_u32(const void* p) {
    uint32_t a;
    asm("{ .reg .u64 t; cvta.to.shared.u64 t, %1; cvt.u32.u64 %0, t; }" : "=r"(a) : "l"(p));
    return a;
}
__device__ __forceinline__ void cp_async16(uint32_t smem, const void* g) {
    asm volatile("cp.async.cg.shared.global [%0], [%1], 16;\n" :: "r"(smem), "l"(g));
}
#define CP_COMMIT() asm volatile("cp.async.commit_group;\n" ::: "memory")
#define CP_WAIT(n)  asm volatile("cp.async.wait_group %0;\n" :: "n"(n) : "memory")

#define LDSM4(r0, r1, r2, r3, addr) \
    asm volatile("ldmatrix.sync.aligned.m8n8.x4.shared.b16 {%0,%1,%2,%3}, [%4];\n" \
                 : "=r"(r0), "=r"(r1), "=r"(r2), "=r"(r3) : "r"(addr))

#define MMA16816(c, a, b) \
    asm volatile("mma.sync.aligned.m16n8k16.row.col.f32.bf16.bf16.f32 " \
                 "{%0,%1,%2,%3}, {%4,%5,%6,%7}, {%8,%9}, {%0,%1,%2,%3};\n" \
                 : "+f"((c)[0]), "+f"((c)[1]), "+f"((c)[2]), "+f"((c)[3]) \
                 : "r"((a)[0]), "r"((a)[1]), "r"((a)[2]), "r"((a)[3]), \
                   "r"((b)[0]), "r"((b)[1]))

// ---------------------------------------------------------------------------
// Fused prep kernel: blocks [0, PREP_A_BLOCKS) convert A; the rest fold W.
// ---------------------------------------------------------------------------
#define PREP_A_BLOCKS 4096   // MM*KK/4 / 256
#define PREP_W_BLOCKS 11     // ceil(NPAD / 256)

__global__ void prep_kernel(const float* __restrict__ A,
                            const float* __restrict__ sW, const float* __restrict__ sb,
                            const float* __restrict__ tW, const float* __restrict__ tb) {
    if (blockIdx.x < PREP_A_BLOCKS) {
        int idx = blockIdx.x * 256 + threadIdx.x;  // over MM*KK/4
        float4 v = *(const float4*)(A + (size_t)idx * 4);
        __nv_bfloat162 p0 = __floats2bfloat162_rn(v.x, v.y);
        __nv_bfloat162 p1 = __floats2bfloat162_rn(v.z, v.w);
        uint2 o;
        o.x = *(uint32_t*)&p0;
        o.y = *(uint32_t*)&p1;
        *(uint2*)&g_Abf[(size_t)idx * 4] = o;
        return;
    }
    int n = (blockIdx.x - PREP_A_BLOCKS) * 256 + threadIdx.x;
    if (n >= NPAD) return;
    if (n < NN) {
        g_bp[n] = tb[n] + sb[n % LBL];
        int col = n % LBL;
#pragma unroll 1
        for (int kb = 0; kb < KK / 8; kb++) {
            __nv_bfloat162 p[4];
#pragma unroll
            for (int i = 0; i < 4; i++) {
                int k0 = kb * 8 + 2 * i;
                float v0 = tW[(size_t)k0 * NN + n] + sW[k0 * LBL + col];
                float v1 = tW[(size_t)(k0 + 1) * NN + n] + sW[(k0 + 1) * LBL + col];
                p[i] = __floats2bfloat162_rn(v0, v1);
            }
            *(uint4*)&g_Wpb[n * KK + kb * 8] = *(uint4*)p;
        }
    } else {
        g_bp[n] = 0.f;
        for (int kb = 0; kb < KK / 8; kb++) {
            uint4 z = {0, 0, 0, 0};
            *(uint4*)&g_Wpb[n * KK + kb * 8] = z;
        }
    }
}

// ---------------------------------------------------------------------------
// mma.sync GEMM + exp epilogue (3-stage cp.async pipeline, 1 bar per k-step)
//   X[m, n] = bf16( exp( mask[m] * (A . Wp + bp) ) )
// CTA tile 128x128, K-step 32. 8 warps: warp tile 64(m) x 32(n).
// ---------------------------------------------------------------------------
#define STG_ELEMS 136   // epilogue stage row stride in bf16 (272 B)

__global__ __launch_bounds__(256, 2) void gemm_exp_kernel(const float* __restrict__ mask) {
    __shared__ __align__(128) char sm[49152];

    const int tid = threadIdx.x;
    const int l   = tid & 31;
    const int wid = tid >> 5;
    const int wm  = wid >> 2;   // 0..1
    const int wn  = wid & 3;    // 0..3
    const int m0  = blockIdx.y * 128;
    const int n0  = blockIdx.x * 128;

    const uint32_t smBase = smem_u32(sm);

    const int a_r = (l & 7) + 8 * ((l >> 3) & 1);
    const int a_s = (l >> 4);
    uint32_t a_off[4][2];
#pragma unroll
    for (int i = 0; i < 4; i++)
#pragma unroll
        for (int ks16 = 0; ks16 < 2; ks16++) {
            int r = wm * 64 + 16 * i + a_r;
            int seg = ks16 * 2 + a_s;
            a_off[i][ks16] = r * 64 + ((seg ^ (r & 3)) << 4);
        }
    const int b_r = (l & 7) + 8 * ((l >> 4) & 1);
    const int b_s = (l >> 3) & 1;
    uint32_t b_off[2][2];
#pragma unroll
    for (int jj = 0; jj < 2; jj++)
#pragma unroll
        for (int ks16 = 0; ks16 < 2; ks16++) {
            int r = wn * 32 + 16 * jj + b_r;
            int seg = ks16 * 2 + b_s;
            b_off[jj][ks16] = r * 64 + ((seg ^ (r & 3)) << 4);
        }

    const int c0r = tid >> 2, c0s = tid & 3;
    const int c1r = (tid + 256) >> 2, c1s = tid & 3;
    const uint32_t so0 = c0r * 64 + ((c0s ^ (c0r & 3)) << 4);
    const uint32_t so1 = c1r * 64 + ((c1s ^ (c1r & 3)) << 4);

#define LOAD_STAGE(s, ks) do {                                                        \
        uint32_t bA = smBase + (s) * 16384;                                           \
        uint32_t bW = bA + 8192;                                                      \
        cp_async16(bA + so0, g_Abf + (size_t)(m0 + c0r) * KK + (ks) * 32 + c0s * 8);  \
        cp_async16(bA + so1, g_Abf + (size_t)(m0 + c1r) * KK + (ks) * 32 + c1s * 8);  \
        cp_async16(bW + so0, g_Wpb + (size_t)(n0 + c0r) * KK + (ks) * 32 + c0s * 8);  \
        cp_async16(bW + so1, g_Wpb + (size_t)(n0 + c1r) * KK + (ks) * 32 + c1s * 8);  \
        CP_COMMIT();                                                                  \
    } while (0)

    float acc[4][4][4];
#pragma unroll
    for (int i = 0; i < 4; i++)
#pragma unroll
        for (int j = 0; j < 4; j++)
#pragma unroll
            for (int q = 0; q < 4; q++) acc[i][j][q] = 0.f;

    LOAD_STAGE(0, 0);
    LOAD_STAGE(1, 1);

#pragma unroll 1
    for (int ks = 0; ks < 8; ks++) {
        if (ks < 7) { CP_WAIT(1); } else { CP_WAIT(0); }
        __syncthreads();
        if (ks + 2 < 8) LOAD_STAGE((ks + 2) % 3, ks + 2);

        const uint32_t bA = smBase + (ks % 3) * 16384;
        const uint32_t bW = bA + 8192;

#pragma unroll
        for (int ks16 = 0; ks16 < 2; ks16++) {
            uint32_t a[4][4];
            uint32_t b[4][2];
#pragma unroll
            for (int i = 0; i < 4; i++)
                LDSM4(a[i][0], a[i][1], a[i][2], a[i][3], bA + a_off[i][ks16]);
#pragma unroll
            for (int jj = 0; jj < 2; jj++)
                LDSM4(b[2 * jj][0], b[2 * jj][1], b[2 * jj + 1][0], b[2 * jj + 1][1],
                      bW + b_off[jj][ks16]);
#pragma unroll
            for (int i = 0; i < 4; i++)
#pragma unroll
                for (int j = 0; j < 4; j++)
                    MMA16816(acc[i][j], a[i], b[j]);
        }
    }
    __syncthreads();

    // Epilogue: exp(mask*(acc+bias)) -> bf16, stage via smem, coalesced write
    __nv_bfloat16* stage = (__nv_bfloat16*)sm;
    const int qr = l >> 2, qc = l & 3;

    float bj0[4], bj1[4];
#pragma unroll
    for (int j = 0; j < 4; j++) {
        int n = n0 + wn * 32 + 8 * j + 2 * qc;
        bj0[j] = g_bp[n];
        bj1[j] = g_bp[n + 1];
    }

#pragma unroll
    for (int i = 0; i < 4; i++) {
        int mlo = wm * 64 + 16 * i + qr;
        float mk_lo = mask[m0 + mlo];
        float mk_hi = mask[m0 + mlo + 8];
#pragma unroll
        for (int j = 0; j < 4; j++) {
            int nl = wn * 32 + 8 * j + 2 * qc;
            float f00 = __expf(mk_lo * (acc[i][j][0] + bj0[j]));
            float f01 = __expf(mk_lo * (acc[i][j][1] + bj1[j]));
            float f10 = __expf(mk_hi * (acc[i][j][2] + bj0[j]));
            float f11 = __expf(mk_hi * (acc[i][j][3] + bj1[j]));
            *(__nv_bfloat162*)&stage[mlo * STG_ELEMS + nl]       = __floats2bfloat162_rn(f00, f01);
            *(__nv_bfloat162*)&stage[(mlo + 8) * STG_ELEMS + nl] = __floats2bfloat162_rn(f10, f11);
        }
    }
    __syncthreads();

#pragma unroll
    for (int h = 0; h < 8; h++) {
        int c = tid + h * 256;
        int row = c >> 4;
        int seg = c & 15;
        uint4 v = *(const uint4*)&stage[row * STG_ELEMS + seg * 8];
        *(uint4*)&g_X[(size_t)(m0 + row) * ESTR + n0 + seg * 8] = v;
    }
}

// ---------------------------------------------------------------------------
// Forward-algorithm scan (bf16 X), ratio recurrence (no log/exp in chain):
//   sa_new[j] = tot[j] / tot[0],   P0 += log(tot[0])
// where tot[j] = sum_i sa[i] * X_t[i,j]. part[j] = P0 + log(sa[j]).
// Binary mask fast paths (m==1 ratio, m==0 skip); exact log fallback otherwise.
// One CTA per batch element; warps 1-7 prefetch (6-buffer, lead 5).
// ---------------------------------------------------------------------------
#define SCAN_CH 326   // 16B chunks covering NN*2 = 5202 bytes

__global__ __launch_bounds__(256) void scan_kernel(const float* __restrict__ mask,
                                                   const int* __restrict__ target,
                                                   float* __restrict__ out) {
    const int b    = blockIdx.x;
    const int tid  = threadIdx.x;
    const int j    = tid & 63;
    const int g    = tid >> 6;
    const int lane = tid & 31;
    const int wid  = tid >> 5;

    __shared__ float sa[64];
    __shared__ float red[256];
    __shared__ float s_mask[TT];
    __shared__ int   s_tg[TT];
    __shared__ float s_tgtE[1];
    __shared__ __align__(16) __nv_bfloat16 buf[6][ESTR];  // 32256B

    const __nv_bfloat16* Xb = g_X + (size_t)b * TT * ESTR;

    s_mask[tid] = mask[b * TT + tid];
    s_tg[tid]   = target[b * TT + tid];

    if (wid > 0) {
        const int c0 = tid - 32;  // 0..223
#pragma unroll 1
        for (int r = 1; r <= 5; r++) {
            const char* src = (const char*)(Xb + (size_t)r * ESTR);
            uint32_t dst = smem_u32(buf[r]);
            for (int c = c0; c < SCAN_CH; c += 224) cp_async16(dst + c * 16, src + c * 16);
            CP_COMMIT();
        }
    }

    __syncthreads();  // s_tg/s_mask visible to all

    // t=0 init: sa[j] = X0[L-1,j] / X0[L-1,0]; P0 = log(X0[L-1,0])
    float P0 = 0.f, tgtE_reg = 0.f;
    if (wid == 0) {
        float v0 = (lane < LBL) ? __bfloat162float(Xb[(LBL - 1) * LBL + lane]) : 1.f;
        float v1 = (lane + 32 < LBL) ? __bfloat162float(Xb[(LBL - 1) * LBL + lane + 32]) : 1.f;
        float vr = __shfl_sync(0xffffffffu, v0, 0);
        float inv = __fdividef(1.f, vr);
        if (lane < LBL)      sa[lane]      = v0 * inv;
        if (lane + 32 < LBL) sa[lane + 32] = v1 * inv;
        P0 = __logf(vr);
    }
    if (tid == 255)
        tgtE_reg = __logf(__bfloat162float(Xb[(LBL - 1) * LBL + s_tg[0]]));
    // (sa visibility guaranteed by the first loop barrier)

#pragma unroll 1
    for (int t = 1; t < TT; t++) {
        if (wid > 0) {
            const int tf = (t + 5 < TT) ? (t + 5) : (TT - 1);
            const char* src = (const char*)(Xb + (size_t)tf * ESTR);
            uint32_t dst = smem_u32(buf[(t + 5) % 6]);
            const int c0 = tid - 32;
            for (int c = c0; c < SCAN_CH; c += 224) cp_async16(dst + c * 16, src + c * 16);
            CP_COMMIT();
            CP_WAIT(5);
        }
        __syncthreads();  // (1) buf[t%6] ready; sa from previous step visible

        const __nv_bfloat16* Xc = buf[t % 6];

        float s = 0.f, s2 = 0.f;
        if (j < LBL) {
#pragma unroll
            for (int it = 0; it < 13; it++) {
                int i = g + 4 * it;
                if (i < LBL) {
                    float v = sa[i] * __bfloat162float(Xc[i * LBL + j]);
                    if (it & 1) s2 += v; else s += v;
                }
            }
            s += s2;
        }
        red[tid] = s;
        if (tid == 255)
            tgtE_reg += __logf(__bfloat162float(Xc[s_tg[t - 1] * LBL + s_tg[t]]));
        __syncthreads();  // (2) partials ready

        if (wid == 0) {
            const float m = s_mask[t];
            float tot0 = red[lane] + red[lane + 64] + red[lane + 128] + red[lane + 192];
            float tot1 = red[lane + 32] + red[lane + 96] + red[lane + 160] + red[lane + 224];
            float tr = __shfl_sync(0xffffffffu, tot0, 0);
            if (m == 1.0f) {
                // Fast path: pure ratio update (no log/exp in chain)
                float inv = __fdividef(1.f, tr);
                if (lane < LBL)      sa[lane]      = tot0 * inv;
                if (lane + 32 < LBL) sa[lane + 32] = tot1 * inv;
                P0 += __logf(tr);          // scalar accumulator, off critical path
            } else if (m != 0.0f) {
                // Exact fractional-mask fallback (log-domain blend)
                float pj0 = (lane < LBL) ? (P0 + __logf(sa[lane])) : -1e30f;
                float pj1 = (lane + 32 < LBL) ? (P0 + __logf(sa[lane + 32])) : -1e30f;
                float pn0 = P0 + __logf(tot0);
                float pn1 = P0 + __logf(tot1);
                pj0 += (pn0 - pj0) * m;
                pj1 += (pn1 - pj1) * m;
                float nr = __shfl_sync(0xffffffffu, pj0, 0);
                if (lane < LBL)      sa[lane]      = __expf(pj0 - nr);
                if (lane + 32 < LBL) sa[lane + 32] = __expf(pj1 - nr);
                P0 = nr;
            }
            // m == 0: sa and P0 unchanged
        }
        // next iteration's barrier (1) protects sa
    }

    if (tid == 255) s_tgtE[0] = tgtE_reg;
    __syncthreads();

    if (wid == 0) {
        // out = P0 + log(sum_j sa[j]) - tgtE   (sa > 0, no max-shift needed)
        float sm = 0.f;
        if (lane < LBL)      sm += sa[lane];
        if (lane + 32 < LBL) sm += sa[lane + 32];
#pragma unroll
        for (int o = 16; o > 0; o >>= 1)
            sm += __shfl_xor_sync(0xffffffffu, sm, o);
        if (lane == 0) out[b] = P0 + __logf(sm) - s_tgtE[0];
    }
}

// ---------------------------------------------------------------------------
extern "C" void kernel_launch(void* const* d_in, const int* in_sizes, int n_in,
                              void* d_out, int out_size) {
    const float* input  = (const float*)d_in[0];
    const float* mask   = (const float*)d_in[1];
    const int*   target = (const int*)d_in[2];
    const float* sW     = (const float*)d_in[3];
    const float* sb     = (const float*)d_in[4];
    const float* tW     = (const float*)d_in[5];
    const float* tb     = (const float*)d_in[6];
    float* out = (float*)d_out;

    (void)in_sizes; (void)n_in; (void)out_size;

    prep_kernel<<<PREP_A_BLOCKS + PREP_W_BLOCKS, 256>>>(input, sW, sb, tW, tb);

    dim3 ggrid(NPAD / 128, MM / 128);  // (21, 128)
    gemm_exp_kernel<<<ggrid, 256>>>(mask);

    scan_kernel<<<BB, 256>>>(mask, target, out);
}

// round 7
// speedup vs baseline: 2.5174x; 1.0081x over previous
#include <cuda_runtime.h>
#include <cuda_bf16.h>
#include <cstdint>

// Problem constants
#define BB    64
#define TT    256
#define KK    256      // INPUT_SIZE
#define LBL   51       // L
#define NN    2601     // L*L
#define NPAD  2688     // 21 * 128
#define ESTR  2688     // X row stride (bf16 elems) = 5376 B
#define MM    16384    // B*T

// ---------------------------------------------------------------------------
// Device globals (no allocations allowed)
// ---------------------------------------------------------------------------
__device__ __align__(256) __nv_bfloat16 g_Abf[MM * KK];          // input, bf16
__device__ __align__(256) __nv_bfloat16 g_Wpb[NPAD * KK];        // folded W, [n][k] bf16
__device__ __align__(256) float         g_bp[NPAD];              // folded bias
__device__ __align__(256) __nv_bfloat16 g_X[(size_t)MM * ESTR];  // exp(mask*energy) (~88MB)

// ---------------------------------------------------------------------------
// Helpers (family-portable PTX only: cp.async, ldmatrix, mma.sync)
// ---------------------------------------------------------------------------
__device__ __forceinline__ uint32_t smem_u32(const void* p) {
    uint32_t a;
    asm("{ .reg .u64 t; cvta.to.shared.u64 t, %1; cvt.u32.u64 %0, t; }" : "=r"(a) : "l"(p));
    return a;
}
__device__ __forceinline__ void cp_async16(uint32_t smem, const void* g) {
    asm volatile("cp.async.cg.shared.global [%0], [%1], 16;\n" :: "r"(smem), "l"(g));
}
#define CP_COMMIT() asm volatile("cp.async.commit_group;\n" ::: "memory")
#define CP_WAIT(n)  asm volatile("cp.async.wait_group %0;\n" :: "n"(n) : "memory")

#define LDSM4(r0, r1, r2, r3, addr) \
    asm volatile("ldmatrix.sync.aligned.m8n8.x4.shared.b16 {%0,%1,%2,%3}, [%4];\n" \
                 : "=r"(r0), "=r"(r1), "=r"(r2), "=r"(r3) : "r"(addr))

#define MMA16816(c, a, b) \
    asm volatile("mma.sync.aligned.m16n8k16.row.col.f32.bf16.bf16.f32 " \
                 "{%0,%1,%2,%3}, {%4,%5,%6,%7}, {%8,%9}, {%0,%1,%2,%3};\n" \
                 : "+f"((c)[0]), "+f"((c)[1]), "+f"((c)[2]), "+f"((c)[3]) \
                 : "r"((a)[0]), "r"((a)[1]), "r"((a)[2]), "r"((a)[3]), \
                   "r"((b)[0]), "r"((b)[1]))

// ---------------------------------------------------------------------------
// Fused prep kernel.
// Blocks [0, PREP_A_BLOCKS): convert A to bf16, 8 independent float4 per
// thread (MLP=8, front-batched). Remaining blocks: fold W + bias.
// ---------------------------------------------------------------------------
#define PREP_A_BLOCKS 512    // 512 * 256 threads * 8 float4 = 1,048,576 = MM*KK/4
#define PREP_W_BLOCKS 11     // ceil(NPAD / 256)

__global__ void prep_kernel(const float* __restrict__ A,
                            const float* __restrict__ sW, const float* __restrict__ sb,
                            const float* __restrict__ tW, const float* __restrict__ tb) {
    if (blockIdx.x < PREP_A_BLOCKS) {
        const size_t base = (size_t)blockIdx.x * 2048 + threadIdx.x;  // float4 index
        const float4* A4 = (const float4*)A;
        float4 v[8];
#pragma unroll
        for (int h = 0; h < 8; h++) v[h] = A4[base + h * 256];   // 8 outstanding loads
#pragma unroll
        for (int h = 0; h < 8; h++) {
            __nv_bfloat162 p0 = __floats2bfloat162_rn(v[h].x, v[h].y);
            __nv_bfloat162 p1 = __floats2bfloat162_rn(v[h].z, v[h].w);
            uint2 o;
            o.x = *(uint32_t*)&p0;
            o.y = *(uint32_t*)&p1;
            *(uint2*)&g_Abf[(base + h * 256) * 4] = o;
        }
        return;
    }
    int n = (blockIdx.x - PREP_A_BLOCKS) * 256 + threadIdx.x;
    if (n >= NPAD) return;
    if (n < NN) {
        g_bp[n] = tb[n] + sb[n % LBL];
        int col = n % LBL;
#pragma unroll 1
        for (int kb = 0; kb < KK / 8; kb++) {
            __nv_bfloat162 p[4];
#pragma unroll
            for (int i = 0; i < 4; i++) {
                int k0 = kb * 8 + 2 * i;
                float v0 = tW[(size_t)k0 * NN + n] + sW[k0 * LBL + col];
                float v1 = tW[(size_t)(k0 + 1) * NN + n] + sW[(k0 + 1) * LBL + col];
                p[i] = __floats2bfloat162_rn(v0, v1);
            }
            *(uint4*)&g_Wpb[n * KK + kb * 8] = *(uint4*)p;
        }
    } else {
        g_bp[n] = 0.f;
        for (int kb = 0; kb < KK / 8; kb++) {
            uint4 z = {0, 0, 0, 0};
            *(uint4*)&g_Wpb[n * KK + kb * 8] = z;
        }
    }
}

// ---------------------------------------------------------------------------
// mma.sync GEMM + exp epilogue (3-stage cp.async pipeline, 1 bar per k-step)
//   X[m, n] = bf16( exp( mask[m] * (A . Wp + bp) ) )
// CTA tile 128x128, K-step 32. 8 warps: warp tile 64(m) x 32(n).
// ---------------------------------------------------------------------------
#define STG_ELEMS 136   // epilogue stage row stride in bf16 (272 B)

__global__ __launch_bounds__(256, 2) void gemm_exp_kernel(const float* __restrict__ mask) {
    __shared__ __align__(128) char sm[49152];

    const int tid = threadIdx.x;
    const int l   = tid & 31;
    const int wid = tid >> 5;
    const int wm  = wid >> 2;   // 0..1
    const int wn  = wid & 3;    // 0..3
    const int m0  = blockIdx.y * 128;
    const int n0  = blockIdx.x * 128;

    const uint32_t smBase = smem_u32(sm);

    const int a_r = (l & 7) + 8 * ((l >> 3) & 1);
    const int a_s = (l >> 4);
    uint32_t a_off[4][2];
#pragma unroll
    for (int i = 0; i < 4; i++)
#pragma unroll
        for (int ks16 = 0; ks16 < 2; ks16++) {
            int r = wm * 64 + 16 * i + a_r;
            int seg = ks16 * 2 + a_s;
            a_off[i][ks16] = r * 64 + ((seg ^ (r & 3)) << 4);
        }
    const int b_r = (l & 7) + 8 * ((l >> 4) & 1);
    const int b_s = (l >> 3) & 1;
    uint32_t b_off[2][2];
#pragma unroll
    for (int jj = 0; jj < 2; jj++)
#pragma unroll
        for (int ks16 = 0; ks16 < 2; ks16++) {
            int r = wn * 32 + 16 * jj + b_r;
            int seg = ks16 * 2 + b_s;
            b_off[jj][ks16] = r * 64 + ((seg ^ (r & 3)) << 4);
        }

    const int c0r = tid >> 2, c0s = tid & 3;
    const int c1r = (tid + 256) >> 2, c1s = tid & 3;
    const uint32_t so0 = c0r * 64 + ((c0s ^ (c0r & 3)) << 4);
    const uint32_t so1 = c1r * 64 + ((c1s ^ (c1r & 3)) << 4);

#define LOAD_STAGE(s, ks) do {                                                        \
        uint32_t bA = smBase + (s) * 16384;                                           \
        uint32_t bW = bA + 8192;                                                      \
        cp_async16(bA + so0, g_Abf + (size_t)(m0 + c0r) * KK + (ks) * 32 + c0s * 8);  \
        cp_async16(bA + so1, g_Abf + (size_t)(m0 + c1r) * KK + (ks) * 32 + c1s * 8);  \
        cp_async16(bW + so0, g_Wpb + (size_t)(n0 + c0r) * KK + (ks) * 32 + c0s * 8);  \
        cp_async16(bW + so1, g_Wpb + (size_t)(n0 + c1r) * KK + (ks) * 32 + c1s * 8);  \
        CP_COMMIT();                                                                  \
    } while (0)

    float acc[4][4][4];
#pragma unroll
    for (int i = 0; i < 4; i++)
#pragma unroll
        for (int j = 0; j < 4; j++)
#pragma unroll
            for (int q = 0; q < 4; q++) acc[i][j][q] = 0.f;

    LOAD_STAGE(0, 0);
    LOAD_STAGE(1, 1);

#pragma unroll 1
    for (int ks = 0; ks < 8; ks++) {
        if (ks < 7) { CP_WAIT(1); } else { CP_WAIT(0); }
        __syncthreads();
        if (ks + 2 < 8) LOAD_STAGE((ks + 2) % 3, ks + 2);

        const uint32_t bA = smBase + (ks % 3) * 16384;
        const uint32_t bW = bA + 8192;

#pragma unroll
        for (int ks16 = 0; ks16 < 2; ks16++) {
            uint32_t a[4][4];
            uint32_t b[4][2];
#pragma unroll
            for (int i = 0; i < 4; i++)
                LDSM4(a[i][0], a[i][1], a[i][2], a[i][3], bA + a_off[i][ks16]);
#pragma unroll
            for (int jj = 0; jj < 2; jj++)
                LDSM4(b[2 * jj][0], b[2 * jj][1], b[2 * jj + 1][0], b[2 * jj + 1][1],
                      bW + b_off[jj][ks16]);
#pragma unroll
            for (int i = 0; i < 4; i++)
#pragma unroll
                for (int j = 0; j < 4; j++)
                    MMA16816(acc[i][j], a[i], b[j]);
        }
    }
    __syncthreads();

    // Epilogue: exp(mask*(acc+bias)) -> bf16, stage via smem, coalesced write
    __nv_bfloat16* stage = (__nv_bfloat16*)sm;
    const int qr = l >> 2, qc = l & 3;

    float bj0[4], bj1[4];
#pragma unroll
    for (int j = 0; j < 4; j++) {
        int n = n0 + wn * 32 + 8 * j + 2 * qc;
        bj0[j] = g_bp[n];
        bj1[j] = g_bp[n + 1];
    }

#pragma unroll
    for (int i = 0; i < 4; i++) {
        int mlo = wm * 64 + 16 * i + qr;
        float mk_lo = mask[m0 + mlo];
        float mk_hi = mask[m0 + mlo + 8];
#pragma unroll
        for (int j = 0; j < 4; j++) {
            int nl = wn * 32 + 8 * j + 2 * qc;
            float f00 = __expf(mk_lo * (acc[i][j][0] + bj0[j]));
            float f01 = __expf(mk_lo * (acc[i][j][1] + bj1[j]));
            float f10 = __expf(mk_hi * (acc[i][j][2] + bj0[j]));
            float f11 = __expf(mk_hi * (acc[i][j][3] + bj1[j]));
            *(__nv_bfloat162*)&stage[mlo * STG_ELEMS + nl]       = __floats2bfloat162_rn(f00, f01);
            *(__nv_bfloat162*)&stage[(mlo + 8) * STG_ELEMS + nl] = __floats2bfloat162_rn(f10, f11);
        }
    }
    __syncthreads();

#pragma unroll
    for (int h = 0; h < 8; h++) {
        int c = tid + h * 256;
        int row = c >> 4;
        int seg = c & 15;
        uint4 v = *(const uint4*)&stage[row * STG_ELEMS + seg * 8];
        *(uint4*)&g_X[(size_t)(m0 + row) * ESTR + n0 + seg * 8] = v;
    }
}

// ---------------------------------------------------------------------------
// Forward-algorithm scan (bf16 X), ratio recurrence (no log/exp in chain):
//   sa_new[j] = tot[j] / tot[0],   P0 += log(tot[0])
// Binary mask fast paths (m==1 ratio, m==0 skip); exact log fallback otherwise.
// One CTA per batch element; warps 1-7 prefetch (6-buffer, lead 5).
// ---------------------------------------------------------------------------
#define SCAN_CH 326   // 16B chunks covering NN*2 = 5202 bytes

__global__ __launch_bounds__(256) void scan_kernel(const float* __restrict__ mask,
                                                   const int* __restrict__ target,
                                                   float* __restrict__ out) {
    const int b    = blockIdx.x;
    const int tid  = threadIdx.x;
    const int j    = tid & 63;
    const int g    = tid >> 6;
    const int lane = tid & 31;
    const int wid  = tid >> 5;

    __shared__ float sa[64];
    __shared__ float red[256];
    __shared__ float s_mask[TT];
    __shared__ int   s_tg[TT];
    __shared__ float s_tgtE[1];
    __shared__ __align__(16) __nv_bfloat16 buf[6][ESTR];  // 32256B

    const __nv_bfloat16* Xb = g_X + (size_t)b * TT * ESTR;

    s_mask[tid] = mask[b * TT + tid];
    s_tg[tid]   = target[b * TT + tid];

    if (wid > 0) {
        const int c0 = tid - 32;  // 0..223
#pragma unroll 1
        for (int r = 1; r <= 5; r++) {
            const char* src = (const char*)(Xb + (size_t)r * ESTR);
            uint32_t dst = smem_u32(buf[r]);
            for (int c = c0; c < SCAN_CH; c += 224) cp_async16(dst + c * 16, src + c * 16);
            CP_COMMIT();
        }
    }

    __syncthreads();  // s_tg/s_mask visible to all

    // t=0 init: sa[j] = X0[L-1,j] / X0[L-1,0]; P0 = log(X0[L-1,0])
    float P0 = 0.f, tgtE_reg = 0.f;
    if (wid == 0) {
        float v0 = (lane < LBL) ? __bfloat162float(Xb[(LBL - 1) * LBL + lane]) : 1.f;
        float v1 = (lane + 32 < LBL) ? __bfloat162float(Xb[(LBL - 1) * LBL + lane + 32]) : 1.f;
        float vr = __shfl_sync(0xffffffffu, v0, 0);
        float inv = __fdividef(1.f, vr);
        if (lane < LBL)      sa[lane]      = v0 * inv;
        if (lane + 32 < LBL) sa[lane + 32] = v1 * inv;
        P0 = __logf(vr);
    }
    if (tid == 255)
        tgtE_reg = __logf(__bfloat162float(Xb[(LBL - 1) * LBL + s_tg[0]]));
    // (sa visibility guaranteed by the first loop barrier)

#pragma unroll 1
    for (int t = 1; t < TT; t++) {
        if (wid > 0) {
            const int tf = (t + 5 < TT) ? (t + 5) : (TT - 1);
            const char* src = (const char*)(Xb + (size_t)tf * ESTR);
            uint32_t dst = smem_u32(buf[(t + 5) % 6]);
            const int c0 = tid - 32;
            for (int c = c0; c < SCAN_CH; c += 224) cp_async16(dst + c * 16, src + c * 16);
            CP_COMMIT();
            CP_WAIT(5);
        }
        __syncthreads();  // (1) buf[t%6] ready; sa from previous step visible

        const __nv_bfloat16* Xc = buf[t % 6];

        float s = 0.f, s2 = 0.f;
        if (j < LBL) {
#pragma unroll
            for (int it = 0; it < 13; it++) {
                int i = g + 4 * it;
                if (i < LBL) {
                    float v = sa[i] * __bfloat162float(Xc[i * LBL + j]);
                    if (it & 1) s2 += v; else s += v;
                }
            }
            s += s2;
        }
        red[tid] = s;
        if (tid == 255)
            tgtE_reg += __logf(__bfloat162float(Xc[s_tg[t - 1] * LBL + s_tg[t]]));
        __syncthreads();  // (2) partials ready

        if (wid == 0) {
            const float m = s_mask[t];
            float tot0 = red[lane] + red[lane + 64] + red[lane + 128] + red[lane + 192];
            float tot1 = red[lane + 32] + red[lane + 96] + red[lane + 160] + red[lane + 224];
            float tr = __shfl_sync(0xffffffffu, tot0, 0);
            if (m == 1.0f) {
                float inv = __fdividef(1.f, tr);
                if (lane < LBL)      sa[lane]      = tot0 * inv;
                if (lane + 32 < LBL) sa[lane + 32] = tot1 * inv;
                P0 += __logf(tr);          // off critical path
            } else if (m != 0.0f) {
                float pj0 = (lane < LBL) ? (P0 + __logf(sa[lane])) : -1e30f;
                float pj1 = (lane + 32 < LBL) ? (P0 + __logf(sa[lane + 32])) : -1e30f;
                float pn0 = P0 + __logf(tot0);
                float pn1 = P0 + __logf(tot1);
                pj0 += (pn0 - pj0) * m;
                pj1 += (pn1 - pj1) * m;
                float nr = __shfl_sync(0xffffffffu, pj0, 0);
                if (lane < LBL)      sa[lane]      = __expf(pj0 - nr);
                if (lane + 32 < LBL) sa[lane + 32] = __expf(pj1 - nr);
                P0 = nr;
            }
            // m == 0: unchanged
        }
        // next iteration's barrier (1) protects sa
    }

    if (tid == 255) s_tgtE[0] = tgtE_reg;
    __syncthreads();

    if (wid == 0) {
        float sm = 0.f;
        if (lane < LBL)      sm += sa[lane];
        if (lane + 32 < LBL) sm += sa[lane + 32];
#pragma unroll
        for (int o = 16; o > 0; o >>= 1)
            sm += __shfl_xor_sync(0xffffffffu, sm, o);
        if (lane == 0) out[b] = P0 + __logf(sm) - s_tgtE[0];
    }
}

// ---------------------------------------------------------------------------
extern "C" void kernel_launch(void* const* d_in, const int* in_sizes, int n_in,
                              void* d_out, int out_size) {
    const float* input  = (const float*)d_in[0];
    const float* mask   = (const float*)d_in[1];
    const int*   target = (const int*)d_in[2];
    const float* sW     = (const float*)d_in[3];
    const float* sb     = (const float*)d_in[4];
    const float* tW     = (const float*)d_in[5];
    const float* tb     = (const float*)d_in[6];
    float* out = (float*)d_out;

    (void)in_sizes; (void)n_in; (void)out_size;

    prep_kernel<<<PREP_A_BLOCKS + PREP_W_BLOCKS, 256>>>(input, sW, sb, tW, tb);

    dim3 ggrid(NPAD / 128, MM / 128);  // (21, 128)
    gemm_exp_kernel<<<ggrid, 256>>>(mask);

    scan_kernel<<<BB, 256>>>(mask, target, out);
}

// round 8
// speedup vs baseline: 3.0792x; 1.2232x over previous
#include <cuda_runtime.h>
#include <cuda_bf16.h>
#include <cstdint>

// Problem constants
#define BB    64
#define TT    256
#define KK    256      // INPUT_SIZE
#define LBL   51       // L
#define NN    2601     // L*L
#define NPAD  2688     // 21 * 128
#define ESTR  2688     // X row stride (bf16 elems) = 5376 B
#define MM    16384    // B*T

// ---------------------------------------------------------------------------
// Device globals (no allocations allowed)
// ---------------------------------------------------------------------------
__device__ __align__(256) __nv_bfloat16 g_Abf[MM * KK];          // input, bf16
__device__ __align__(256) __nv_bfloat16 g_Wpb[NPAD * KK];        // folded W, [n][k] bf16
__device__ __align__(256) float         g_bp[NPAD];              // folded bias
__device__ __align__(256) __nv_bfloat16 g_X[(size_t)MM * ESTR];  // exp(mask*energy) (~88MB)

// ---------------------------------------------------------------------------
// Helpers (family-portable PTX only: cp.async, ldmatrix, mma.sync)
// ---------------------------------------------------------------------------
__device__ __forceinline__ uint32_t smem_u32(const void* p) {
    uint32_t a;
    asm("{ .reg .u64 t; cvta.to.shared.u64 t, %1; cvt.u32.u64 %0, t; }" : "=r"(a) : "l"(p));
    return a;
}
__device__ __forceinline__ void cp_async16(uint32_t smem, const void* g) {
    asm volatile("cp.async.cg.shared.global [%0], [%1], 16;\n" :: "r"(smem), "l"(g));
}
#define CP_COMMIT() asm volatile("cp.async.commit_group;\n" ::: "memory")
#define CP_WAIT(n)  asm volatile("cp.async.wait_group %0;\n" :: "n"(n) : "memory")

#define LDSM4(r0, r1, r2, r3, addr) \
    asm volatile("ldmatrix.sync.aligned.m8n8.x4.shared.b16 {%0,%1,%2,%3}, [%4];\n" \
                 : "=r"(r0), "=r"(r1), "=r"(r2), "=r"(r3) : "r"(addr))

#define MMA16816(c, a, b) \
    asm volatile("mma.sync.aligned.m16n8k16.row.col.f32.bf16.bf16.f32 " \
                 "{%0,%1,%2,%3}, {%4,%5,%6,%7}, {%8,%9}, {%0,%1,%2,%3};\n" \
                 : "+f"((c)[0]), "+f"((c)[1]), "+f"((c)[2]), "+f"((c)[3]) \
                 : "r"((a)[0]), "r"((a)[1]), "r"((a)[2]), "r"((a)[3]), \
                   "r"((b)[0]), "r"((b)[1]))

// ---------------------------------------------------------------------------
// Fused prep kernel.
// Blocks [0, PREP_A_BLOCKS): convert A to bf16, 8 front-batched float4/thread.
// Blocks [PREP_A_BLOCKS, +PREP_W_BLOCKS): W-fold, one (n, kb) pair per thread
// (fully parallel: 16 independent loads, one 16B store, no serial loop).
// ---------------------------------------------------------------------------
#define PREP_A_BLOCKS 512    // 512 * 256 * 8 float4 = MM*KK/4
#define PREP_W_BLOCKS 336    // 2688 n * 32 kb / 256

__global__ __launch_bounds__(256, 1) void prep_kernel(
        const float* __restrict__ A,
        const float* __restrict__ sW, const float* __restrict__ sb,
        const float* __restrict__ tW, const float* __restrict__ tb) {
    if (blockIdx.x < PREP_A_BLOCKS) {
        const size_t base = (size_t)blockIdx.x * 2048 + threadIdx.x;  // float4 index
        const float4* A4 = (const float4*)A;
        float4 v[8];
#pragma unroll
        for (int h = 0; h < 8; h++) v[h] = A4[base + h * 256];   // 8 outstanding loads
#pragma unroll
        for (int h = 0; h < 8; h++) {
            __nv_bfloat162 p0 = __floats2bfloat162_rn(v[h].x, v[h].y);
            __nv_bfloat162 p1 = __floats2bfloat162_rn(v[h].z, v[h].w);
            uint2 o;
            o.x = *(uint32_t*)&p0;
            o.y = *(uint32_t*)&p1;
            *(uint2*)&g_Abf[(base + h * 256) * 4] = o;
        }
        return;
    }
    // W-fold: idx -> (kb, n); consecutive threads share kb, walk n (coalesced tW)
    const int idx = (blockIdx.x - PREP_A_BLOCKS) * 256 + threadIdx.x;  // 0..86015
    const int kb  = idx / NPAD;        // 0..31
    const int n   = idx - kb * NPAD;   // 0..2687
    if (n < NN) {
        const int col = n % LBL;
        if (kb == 0) g_bp[n] = tb[n] + sb[col];
        float v[8], w[8];
#pragma unroll
        for (int i = 0; i < 8; i++)
            v[i] = tW[(size_t)(kb * 8 + i) * NN + n];    // 8 independent, coalesced
#pragma unroll
        for (int i = 0; i < 8; i++)
            w[i] = sW[(kb * 8 + i) * LBL + col];         // 8 independent
        __nv_bfloat162 p[4];
#pragma unroll
        for (int i = 0; i < 4; i++)
            p[i] = __floats2bfloat162_rn(v[2 * i] + w[2 * i], v[2 * i + 1] + w[2 * i + 1]);
        *(uint4*)&g_Wpb[n * KK + kb * 8] = *(uint4*)p;
    } else {
        if (kb == 0) g_bp[n] = 0.f;
        uint4 z = {0, 0, 0, 0};
        *(uint4*)&g_Wpb[n * KK + kb * 8] = z;
    }
}

// ---------------------------------------------------------------------------
// mma.sync GEMM + exp epilogue (3-stage cp.async pipeline, 1 bar per k-step)
//   X[m, n] = bf16( exp( mask[m] * (A . Wp + bp) ) )
// CTA tile 128x128, K-step 32. 8 warps: warp tile 64(m) x 32(n).
// ---------------------------------------------------------------------------
#define STG_ELEMS 136   // epilogue stage row stride in bf16 (272 B)

__global__ __launch_bounds__(256, 2) void gemm_exp_kernel(const float* __restrict__ mask) {
    __shared__ __align__(128) char sm[49152];

    const int tid = threadIdx.x;
    const int l   = tid & 31;
    const int wid = tid >> 5;
    const int wm  = wid >> 2;   // 0..1
    const int wn  = wid & 3;    // 0..3
    const int m0  = blockIdx.y * 128;
    const int n0  = blockIdx.x * 128;

    const uint32_t smBase = smem_u32(sm);

    const int a_r = (l & 7) + 8 * ((l >> 3) & 1);
    const int a_s = (l >> 4);
    uint32_t a_off[4][2];
#pragma unroll
    for (int i = 0; i < 4; i++)
#pragma unroll
        for (int ks16 = 0; ks16 < 2; ks16++) {
            int r = wm * 64 + 16 * i + a_r;
            int seg = ks16 * 2 + a_s;
            a_off[i][ks16] = r * 64 + ((seg ^ (r & 3)) << 4);
        }
    const int b_r = (l & 7) + 8 * ((l >> 4) & 1);
    const int b_s = (l >> 3) & 1;
    uint32_t b_off[2][2];
#pragma unroll
    for (int jj = 0; jj < 2; jj++)
#pragma unroll
        for (int ks16 = 0; ks16 < 2; ks16++) {
            int r = wn * 32 + 16 * jj + b_r;
            int seg = ks16 * 2 + b_s;
            b_off[jj][ks16] = r * 64 + ((seg ^ (r & 3)) << 4);
        }

    const int c0r = tid >> 2, c0s = tid & 3;
    const int c1r = (tid + 256) >> 2, c1s = tid & 3;
    const uint32_t so0 = c0r * 64 + ((c0s ^ (c0r & 3)) << 4);
    const uint32_t so1 = c1r * 64 + ((c1s ^ (c1r & 3)) << 4);

#define LOAD_STAGE(s, ks) do {                                                        \
        uint32_t bA = smBase + (s) * 16384;                                           \
        uint32_t bW = bA + 8192;                                                      \
        cp_async16(bA + so0, g_Abf + (size_t)(m0 + c0r) * KK + (ks) * 32 + c0s * 8);  \
        cp_async16(bA + so1, g_Abf + (size_t)(m0 + c1r) * KK + (ks) * 32 + c1s * 8);  \
        cp_async16(bW + so0, g_Wpb + (size_t)(n0 + c0r) * KK + (ks) * 32 + c0s * 8);  \
        cp_async16(bW + so1, g_Wpb + (size_t)(n0 + c1r) * KK + (ks) * 32 + c1s * 8);  \
        CP_COMMIT();                                                                  \
    } while (0)

    float acc[4][4][4];
#pragma unroll
    for (int i = 0; i < 4; i++)
#pragma unroll
        for (int j = 0; j < 4; j++)
#pragma unroll
            for (int q = 0; q < 4; q++) acc[i][j][q] = 0.f;

    LOAD_STAGE(0, 0);
    LOAD_STAGE(1, 1);

#pragma unroll 1
    for (int ks = 0; ks < 8; ks++) {
        if (ks < 7) { CP_WAIT(1); } else { CP_WAIT(0); }
        __syncthreads();
        if (ks + 2 < 8) LOAD_STAGE((ks + 2) % 3, ks + 2);

        const uint32_t bA = smBase + (ks % 3) * 16384;
        const uint32_t bW = bA + 8192;

#pragma unroll
        for (int ks16 = 0; ks16 < 2; ks16++) {
            uint32_t a[4][4];
            uint32_t b[4][2];
#pragma unroll
            for (int i = 0; i < 4; i++)
                LDSM4(a[i][0], a[i][1], a[i][2], a[i][3], bA + a_off[i][ks16]);
#pragma unroll
            for (int jj = 0; jj < 2; jj++)
                LDSM4(b[2 * jj][0], b[2 * jj][1], b[2 * jj + 1][0], b[2 * jj + 1][1],
                      bW + b_off[jj][ks16]);
#pragma unroll
            for (int i = 0; i < 4; i++)
#pragma unroll
                for (int j = 0; j < 4; j++)
                    MMA16816(acc[i][j], a[i], b[j]);
        }
    }
    __syncthreads();

    // Epilogue: exp(mask*(acc+bias)) -> bf16, stage via smem, coalesced write
    __nv_bfloat16* stage = (__nv_bfloat16*)sm;
    const int qr = l >> 2, qc = l & 3;

    float bj0[4], bj1[4];
#pragma unroll
    for (int j = 0; j < 4; j++) {
        int n = n0 + wn * 32 + 8 * j + 2 * qc;
        bj0[j] = g_bp[n];
        bj1[j] = g_bp[n + 1];
    }

#pragma unroll
    for (int i = 0; i < 4; i++) {
        int mlo = wm * 64 + 16 * i + qr;
        float mk_lo = mask[m0 + mlo];
        float mk_hi = mask[m0 + mlo + 8];
#pragma unroll
        for (int j = 0; j < 4; j++) {
            int nl = wn * 32 + 8 * j + 2 * qc;
            float f00 = __expf(mk_lo * (acc[i][j][0] + bj0[j]));
            float f01 = __expf(mk_lo * (acc[i][j][1] + bj1[j]));
            float f10 = __expf(mk_hi * (acc[i][j][2] + bj0[j]));
            float f11 = __expf(mk_hi * (acc[i][j][3] + bj1[j]));
            *(__nv_bfloat162*)&stage[mlo * STG_ELEMS + nl]       = __floats2bfloat162_rn(f00, f01);
            *(__nv_bfloat162*)&stage[(mlo + 8) * STG_ELEMS + nl] = __floats2bfloat162_rn(f10, f11);
        }
    }
    __syncthreads();

#pragma unroll
    for (int h = 0; h < 8; h++) {
        int c = tid + h * 256;
        int row = c >> 4;
        int seg = c & 15;
        uint4 v = *(const uint4*)&stage[row * STG_ELEMS + seg * 8];
        *(uint4*)&g_X[(size_t)(m0 + row) * ESTR + n0 + seg * 8] = v;
    }
}

// ---------------------------------------------------------------------------
// Forward-algorithm scan (bf16 X), ratio recurrence (no log/exp in chain):
//   sa_new[j] = tot[j] / tot[0],   P0 += log(tot[0])
// Binary mask fast paths (m==1 ratio, m==0 skip); exact log fallback otherwise.
// One CTA per batch element; warps 1-7 prefetch (6-buffer, lead 5).
// ---------------------------------------------------------------------------
#define SCAN_CH 326   // 16B chunks covering NN*2 = 5202 bytes

__global__ __launch_bounds__(256) void scan_kernel(const float* __restrict__ mask,
                                                   const int* __restrict__ target,
                                                   float* __restrict__ out) {
    const int b    = blockIdx.x;
    const int tid  = threadIdx.x;
    const int j    = tid & 63;
    const int g    = tid >> 6;
    const int lane = tid & 31;
    const int wid  = tid >> 5;

    __shared__ float sa[64];
    __shared__ float red[256];
    __shared__ float s_mask[TT];
    __shared__ int   s_tg[TT];
    __shared__ float s_tgtE[1];
    __shared__ __align__(16) __nv_bfloat16 buf[6][ESTR];  // 32256B

    const __nv_bfloat16* Xb = g_X + (size_t)b * TT * ESTR;

    s_mask[tid] = mask[b * TT + tid];
    s_tg[tid]   = target[b * TT + tid];

    if (wid > 0) {
        const int c0 = tid - 32;  // 0..223
#pragma unroll 1
        for (int r = 1; r <= 5; r++) {
            const char* src = (const char*)(Xb + (size_t)r * ESTR);
            uint32_t dst = smem_u32(buf[r]);
            for (int c = c0; c < SCAN_CH; c += 224) cp_async16(dst + c * 16, src + c * 16);
            CP_COMMIT();
        }
    }

    __syncthreads();  // s_tg/s_mask visible to all

    // t=0 init: sa[j] = X0[L-1,j] / X0[L-1,0]; P0 = log(X0[L-1,0])
    float P0 = 0.f, tgtE_reg = 0.f;
    if (wid == 0) {
        float v0 = (lane < LBL) ? __bfloat162float(Xb[(LBL - 1) * LBL + lane]) : 1.f;
        float v1 = (lane + 32 < LBL) ? __bfloat162float(Xb[(LBL - 1) * LBL + lane + 32]) : 1.f;
        float vr = __shfl_sync(0xffffffffu, v0, 0);
        float inv = __fdividef(1.f, vr);
        if (lane < LBL)      sa[lane]      = v0 * inv;
        if (lane + 32 < LBL) sa[lane + 32] = v1 * inv;
        P0 = __logf(vr);
    }
    if (tid == 255)
        tgtE_reg = __logf(__bfloat162float(Xb[(LBL - 1) * LBL + s_tg[0]]));
    // (sa visibility guaranteed by the first loop barrier)

#pragma unroll 1
    for (int t = 1; t < TT; t++) {
        if (wid > 0) {
            const int tf = (t + 5 < TT) ? (t + 5) : (TT - 1);
            const char* src = (const char*)(Xb + (size_t)tf * ESTR);
            uint32_t dst = smem_u32(buf[(t + 5) % 6]);
            const int c0 = tid - 32;
            for (int c = c0; c < SCAN_CH; c += 224) cp_async16(dst + c * 16, src + c * 16);
            CP_COMMIT();
            CP_WAIT(5);
        }
        __syncthreads();  // (1) buf[t%6] ready; sa from previous step visible

        const __nv_bfloat16* Xc = buf[t % 6];

        float s = 0.f, s2 = 0.f;
        if (j < LBL) {
#pragma unroll
            for (int it = 0; it < 13; it++) {
                int i = g + 4 * it;
                if (i < LBL) {
                    float v = sa[i] * __bfloat162float(Xc[i * LBL + j]);
                    if (it & 1) s2 += v; else s += v;
                }
            }
            s += s2;
        }
        red[tid] = s;
        if (tid == 255)
            tgtE_reg += __logf(__bfloat162float(Xc[s_tg[t - 1] * LBL + s_tg[t]]));
        __syncthreads();  // (2) partials ready

        if (wid == 0) {
            const float m = s_mask[t];
            float tot0 = red[lane] + red[lane + 64] + red[lane + 128] + red[lane + 192];
            float tot1 = red[lane + 32] + red[lane + 96] + red[lane + 160] + red[lane + 224];
            float tr = __shfl_sync(0xffffffffu, tot0, 0);
            if (m == 1.0f) {
                float inv = __fdividef(1.f, tr);
                if (lane < LBL)      sa[lane]      = tot0 * inv;
                if (lane + 32 < LBL) sa[lane + 32] = tot1 * inv;
                P0 += __logf(tr);          // off critical path
            } else if (m != 0.0f) {
                float pj0 = (lane < LBL) ? (P0 + __logf(sa[lane])) : -1e30f;
                float pj1 = (lane + 32 < LBL) ? (P0 + __logf(sa[lane + 32])) : -1e30f;
                float pn0 = P0 + __logf(tot0);
                float pn1 = P0 + __logf(tot1);
                pj0 += (pn0 - pj0) * m;
                pj1 += (pn1 - pj1) * m;
                float nr = __shfl_sync(0xffffffffu, pj0, 0);
                if (lane < LBL)      sa[lane]      = __expf(pj0 - nr);
                if (lane + 32 < LBL) sa[lane + 32] = __expf(pj1 - nr);
                P0 = nr;
            }
            // m == 0: unchanged
        }
        // next iteration's barrier (1) protects sa
    }

    if (tid == 255) s_tgtE[0] = tgtE_reg;
    __syncthreads();

    if (wid == 0) {
        float sm = 0.f;
        if (lane < LBL)      sm += sa[lane];
        if (lane + 32 < LBL) sm += sa[lane + 32];
#pragma unroll
        for (int o = 16; o > 0; o >>= 1)
            sm += __shfl_xor_sync(0xffffffffu, sm, o);
        if (lane == 0) out[b] = P0 + __logf(sm) - s_tgtE[0];
    }
}

// ---------------------------------------------------------------------------
extern "C" void kernel_launch(void* const* d_in, const int* in_sizes, int n_in,
                              void* d_out, int out_size) {
    const float* input  = (const float*)d_in[0];
    const float* mask   = (const float*)d_in[1];
    const int*   target = (const int*)d_in[2];
    const float* sW     = (const float*)d_in[3];
    const float* sb     = (const float*)d_in[4];
    const float* tW     = (const float*)d_in[5];
    const float* tb     = (const float*)d_in[6];
    float* out = (float*)d_out;

    (void)in_sizes; (void)n_in; (void)out_size;

    prep_kernel<<<PREP_A_BLOCKS + PREP_W_BLOCKS, 256>>>(input, sW, sb, tW, tb);

    dim3 ggrid(NPAD / 128, MM / 128);  // (21, 128)
    gemm_exp_kernel<<<ggrid, 256>>>(mask);

    scan_kernel<<<BB, 256>>>(mask, target, out);
}

// round 9
// speedup vs baseline: 3.0815x; 1.0007x over previous
#include <cuda_runtime.h>
#include <cuda_bf16.h>
#include <cstdint>

// Problem constants
#define BB    64
#define TT    256
#define KK    256      // INPUT_SIZE
#define LBL   51       // L
#define NN    2601     // L*L
#define NPAD  2688     // 21 * 128
#define ESTR  2688     // X row stride (bf16 elems) = 5376 B
#define MM    16384    // B*T

// ---------------------------------------------------------------------------
// Device globals (no allocations allowed)
// ---------------------------------------------------------------------------
__device__ __align__(256) __nv_bfloat16 g_Abf[MM * KK];          // input, bf16
__device__ __align__(256) __nv_bfloat16 g_Wpb[NPAD * KK];        // folded W, [n][k] bf16
__device__ __align__(256) float         g_bp[NPAD];              // folded bias
__device__ __align__(256) __nv_bfloat16 g_X[(size_t)MM * ESTR];  // exp(mask*energy) (~88MB)

// ---------------------------------------------------------------------------
// Helpers (family-portable PTX only: cp.async, ldmatrix, mma.sync)
// ---------------------------------------------------------------------------
__device__ __forceinline__ uint32_t smem_u32(const void* p) {
    uint32_t a;
    asm("{ .reg .u64 t; cvta.to.shared.u64 t, %1; cvt.u32.u64 %0, t; }" : "=r"(a) : "l"(p));
    return a;
}
__device__ __forceinline__ void cp_async16(uint32_t smem, const void* g) {
    asm volatile("cp.async.cg.shared.global [%0], [%1], 16;\n" :: "r"(smem), "l"(g));
}
#define CP_COMMIT() asm volatile("cp.async.commit_group;\n" ::: "memory")
#define CP_WAIT(n)  asm volatile("cp.async.wait_group %0;\n" :: "n"(n) : "memory")

#define LDSM4(r0, r1, r2, r3, addr) \
    asm volatile("ldmatrix.sync.aligned.m8n8.x4.shared.b16 {%0,%1,%2,%3}, [%4];\n" \
                 : "=r"(r0), "=r"(r1), "=r"(r2), "=r"(r3) : "r"(addr))

#define MMA16816(c, a, b) \
    asm volatile("mma.sync.aligned.m16n8k16.row.col.f32.bf16.bf16.f32 " \
                 "{%0,%1,%2,%3}, {%4,%5,%6,%7}, {%8,%9}, {%0,%1,%2,%3};\n" \
                 : "+f"((c)[0]), "+f"((c)[1]), "+f"((c)[2]), "+f"((c)[3]) \
                 : "r"((a)[0]), "r"((a)[1]), "r"((a)[2]), "r"((a)[3]), \
                   "r"((b)[0]), "r"((b)[1]))

// ---------------------------------------------------------------------------
// Fused prep kernel.
// Blocks [0, PREP_A_BLOCKS): convert A to bf16, 8 front-batched float4/thread.
// Blocks [PREP_A_BLOCKS, +PREP_W_BLOCKS): W-fold, one (n, kb) pair per thread
// (fully parallel: 16 independent loads, one 16B store, no serial loop).
// ---------------------------------------------------------------------------
#define PREP_A_BLOCKS 512    // 512 * 256 * 8 float4 = MM*KK/4
#define PREP_W_BLOCKS 336    // 2688 n * 32 kb / 256

__global__ __launch_bounds__(256, 1) void prep_kernel(
        const float* __restrict__ A,
        const float* __restrict__ sW, const float* __restrict__ sb,
        const float* __restrict__ tW, const float* __restrict__ tb) {
    if (blockIdx.x < PREP_A_BLOCKS) {
        const size_t base = (size_t)blockIdx.x * 2048 + threadIdx.x;  // float4 index
        const float4* A4 = (const float4*)A;
        float4 v[8];
#pragma unroll
        for (int h = 0; h < 8; h++) v[h] = A4[base + h * 256];   // 8 outstanding loads
#pragma unroll
        for (int h = 0; h < 8; h++) {
            __nv_bfloat162 p0 = __floats2bfloat162_rn(v[h].x, v[h].y);
            __nv_bfloat162 p1 = __floats2bfloat162_rn(v[h].z, v[h].w);
            uint2 o;
            o.x = *(uint32_t*)&p0;
            o.y = *(uint32_t*)&p1;
            *(uint2*)&g_Abf[(base + h * 256) * 4] = o;
        }
        return;
    }
    // W-fold: idx -> (kb, n); consecutive threads share kb, walk n (coalesced tW)
    const int idx = (blockIdx.x - PREP_A_BLOCKS) * 256 + threadIdx.x;  // 0..86015
    const int kb  = idx / NPAD;        // 0..31
    const int n   = idx - kb * NPAD;   // 0..2687
    if (n < NN) {
        const int col = n % LBL;
        if (kb == 0) g_bp[n] = tb[n] + sb[col];
        float v[8], w[8];
#pragma unroll
        for (int i = 0; i < 8; i++)
            v[i] = tW[(size_t)(kb * 8 + i) * NN + n];    // 8 independent, coalesced
#pragma unroll
        for (int i = 0; i < 8; i++)
            w[i] = sW[(kb * 8 + i) * LBL + col];         // 8 independent
        __nv_bfloat162 p[4];
#pragma unroll
        for (int i = 0; i < 4; i++)
            p[i] = __floats2bfloat162_rn(v[2 * i] + w[2 * i], v[2 * i + 1] + w[2 * i + 1]);
        *(uint4*)&g_Wpb[n * KK + kb * 8] = *(uint4*)p;
    } else {
        if (kb == 0) g_bp[n] = 0.f;
        uint4 z = {0, 0, 0, 0};
        *(uint4*)&g_Wpb[n * KK + kb * 8] = z;
    }
}

// ---------------------------------------------------------------------------
// mma.sync GEMM + exp epilogue (3-stage cp.async pipeline, 1 bar per k-step)
//   X[m, n] = bf16( exp( mask[m] * (A . Wp + bp) ) )
// CTA tile 128x128, K-step 32. 8 warps: warp tile 64(m) x 32(n).
// ---------------------------------------------------------------------------
#define STG_ELEMS 136   // epilogue stage row stride in bf16 (272 B)

__global__ __launch_bounds__(256, 2) void gemm_exp_kernel(const float* __restrict__ mask) {
    __shared__ __align__(128) char sm[49152];

    const int tid = threadIdx.x;
    const int l   = tid & 31;
    const int wid = tid >> 5;
    const int wm  = wid >> 2;   // 0..1
    const int wn  = wid & 3;    // 0..3
    const int m0  = blockIdx.y * 128;
    const int n0  = blockIdx.x * 128;

    const uint32_t smBase = smem_u32(sm);

    const int a_r = (l & 7) + 8 * ((l >> 3) & 1);
    const int a_s = (l >> 4);
    uint32_t a_off[4][2];
#pragma unroll
    for (int i = 0; i < 4; i++)
#pragma unroll
        for (int ks16 = 0; ks16 < 2; ks16++) {
            int r = wm * 64 + 16 * i + a_r;
            int seg = ks16 * 2 + a_s;
            a_off[i][ks16] = r * 64 + ((seg ^ (r & 3)) << 4);
        }
    const int b_r = (l & 7) + 8 * ((l >> 4) & 1);
    const int b_s = (l >> 3) & 1;
    uint32_t b_off[2][2];
#pragma unroll
    for (int jj = 0; jj < 2; jj++)
#pragma unroll
        for (int ks16 = 0; ks16 < 2; ks16++) {
            int r = wn * 32 + 16 * jj + b_r;
            int seg = ks16 * 2 + b_s;
            b_off[jj][ks16] = r * 64 + ((seg ^ (r & 3)) << 4);
        }

    const int c0r = tid >> 2, c0s = tid & 3;
    const int c1r = (tid + 256) >> 2, c1s = tid & 3;
    const uint32_t so0 = c0r * 64 + ((c0s ^ (c0r & 3)) << 4);
    const uint32_t so1 = c1r * 64 + ((c1s ^ (c1r & 3)) << 4);

#define LOAD_STAGE(s, ks) do {                                                        \
        uint32_t bA = smBase + (s) * 16384;                                           \
        uint32_t bW = bA + 8192;                                                      \
        cp_async16(bA + so0, g_Abf + (size_t)(m0 + c0r) * KK + (ks) * 32 + c0s * 8);  \
        cp_async16(bA + so1, g_Abf + (size_t)(m0 + c1r) * KK + (ks) * 32 + c1s * 8);  \
        cp_async16(bW + so0, g_Wpb + (size_t)(n0 + c0r) * KK + (ks) * 32 + c0s * 8);  \
        cp_async16(bW + so1, g_Wpb + (size_t)(n0 + c1r) * KK + (ks) * 32 + c1s * 8);  \
        CP_COMMIT();                                                                  \
    } while (0)

    float acc[4][4][4];
#pragma unroll
    for (int i = 0; i < 4; i++)
#pragma unroll
        for (int j = 0; j < 4; j++)
#pragma unroll
            for (int q = 0; q < 4; q++) acc[i][j][q] = 0.f;

    LOAD_STAGE(0, 0);
    LOAD_STAGE(1, 1);

#pragma unroll 1
    for (int ks = 0; ks < 8; ks++) {
        if (ks < 7) { CP_WAIT(1); } else { CP_WAIT(0); }
        __syncthreads();
        if (ks + 2 < 8) LOAD_STAGE((ks + 2) % 3, ks + 2);

        const uint32_t bA = smBase + (ks % 3) * 16384;
        const uint32_t bW = bA + 8192;

#pragma unroll
        for (int ks16 = 0; ks16 < 2; ks16++) {
            uint32_t a[4][4];
            uint32_t b[4][2];
#pragma unroll
            for (int i = 0; i < 4; i++)
                LDSM4(a[i][0], a[i][1], a[i][2], a[i][3], bA + a_off[i][ks16]);
#pragma unroll
            for (int jj = 0; jj < 2; jj++)
                LDSM4(b[2 * jj][0], b[2 * jj][1], b[2 * jj + 1][0], b[2 * jj + 1][1],
                      bW + b_off[jj][ks16]);
#pragma unroll
            for (int i = 0; i < 4; i++)
#pragma unroll
                for (int j = 0; j < 4; j++)
                    MMA16816(acc[i][j], a[i], b[j]);
        }
    }
    __syncthreads();

    // Epilogue: exp(mask*(acc+bias)) -> bf16, stage via smem, coalesced write
    __nv_bfloat16* stage = (__nv_bfloat16*)sm;
    const int qr = l >> 2, qc = l & 3;

    float bj0[4], bj1[4];
#pragma unroll
    for (int j = 0; j < 4; j++) {
        int n = n0 + wn * 32 + 8 * j + 2 * qc;
        bj0[j] = g_bp[n];
        bj1[j] = g_bp[n + 1];
    }

#pragma unroll
    for (int i = 0; i < 4; i++) {
        int mlo = wm * 64 + 16 * i + qr;
        float mk_lo = mask[m0 + mlo];
        float mk_hi = mask[m0 + mlo + 8];
#pragma unroll
        for (int j = 0; j < 4; j++) {
            int nl = wn * 32 + 8 * j + 2 * qc;
            float f00 = __expf(mk_lo * (acc[i][j][0] + bj0[j]));
            float f01 = __expf(mk_lo * (acc[i][j][1] + bj1[j]));
            float f10 = __expf(mk_hi * (acc[i][j][2] + bj0[j]));
            float f11 = __expf(mk_hi * (acc[i][j][3] + bj1[j]));
            *(__nv_bfloat162*)&stage[mlo * STG_ELEMS + nl]       = __floats2bfloat162_rn(f00, f01);
            *(__nv_bfloat162*)&stage[(mlo + 8) * STG_ELEMS + nl] = __floats2bfloat162_rn(f10, f11);
        }
    }
    __syncthreads();

#pragma unroll
    for (int h = 0; h < 8; h++) {
        int c = tid + h * 256;
        int row = c >> 4;
        int seg = c & 15;
        uint4 v = *(const uint4*)&stage[row * STG_ELEMS + seg * 8];
        *(uint4*)&g_X[(size_t)(m0 + row) * ESTR + n0 + seg * 8] = v;
    }
}

// ---------------------------------------------------------------------------
// Forward-algorithm scan (bf16 X), ratio recurrence (no log/exp in chain):
//   sa_new[j] = tot[j] / tot[0],   P0 += log(tot[0])
// Binary mask fast paths (m==1 ratio, m==0 skip); exact log fallback otherwise.
// One CTA per batch element; warps 1-7 prefetch (6-buffer, lead 5).
// ---------------------------------------------------------------------------
#define SCAN_CH 326   // 16B chunks covering NN*2 = 5202 bytes

__global__ __launch_bounds__(256) void scan_kernel(const float* __restrict__ mask,
                                                   const int* __restrict__ target,
                                                   float* __restrict__ out) {
    const int b    = blockIdx.x;
    const int tid  = threadIdx.x;
    const int j    = tid & 63;
    const int g    = tid >> 6;
    const int lane = tid & 31;
    const int wid  = tid >> 5;

    __shared__ float sa[64];
    __shared__ float red[256];
    __shared__ float s_mask[TT];
    __shared__ int   s_tg[TT];
    __shared__ float s_tgtE[1];
    __shared__ __align__(16) __nv_bfloat16 buf[6][ESTR];  // 32256B

    const __nv_bfloat16* Xb = g_X + (size_t)b * TT * ESTR;

    s_mask[tid] = mask[b * TT + tid];
    s_tg[tid]   = target[b * TT + tid];

    if (wid > 0) {
        const int c0 = tid - 32;  // 0..223
#pragma unroll 1
        for (int r = 1; r <= 5; r++) {
            const char* src = (const char*)(Xb + (size_t)r * ESTR);
            uint32_t dst = smem_u32(buf[r]);
            for (int c = c0; c < SCAN_CH; c += 224) cp_async16(dst + c * 16, src + c * 16);
            CP_COMMIT();
        }
    }

    __syncthreads();  // s_tg/s_mask visible to all

    // t=0 init: sa[j] = X0[L-1,j] / X0[L-1,0]; P0 = log(X0[L-1,0])
    float P0 = 0.f, tgtE_reg = 0.f;
    if (wid == 0) {
        float v0 = (lane < LBL) ? __bfloat162float(Xb[(LBL - 1) * LBL + lane]) : 1.f;
        float v1 = (lane + 32 < LBL) ? __bfloat162float(Xb[(LBL - 1) * LBL + lane + 32]) : 1.f;
        float vr = __shfl_sync(0xffffffffu, v0, 0);
        float inv = __fdividef(1.f, vr);
        if (lane < LBL)      sa[lane]      = v0 * inv;
        if (lane + 32 < LBL) sa[lane + 32] = v1 * inv;
        P0 = __logf(vr);
    }
    if (tid == 255)
        tgtE_reg = __logf(__bfloat162float(Xb[(LBL - 1) * LBL + s_tg[0]]));
    // (sa visibility guaranteed by the first loop barrier)

#pragma unroll 1
    for (int t = 1; t < TT; t++) {
        if (wid > 0) {
            const int tf = (t + 5 < TT) ? (t + 5) : (TT - 1);
            const char* src = (const char*)(Xb + (size_t)tf * ESTR);
            uint32_t dst = smem_u32(buf[(t + 5) % 6]);
            const int c0 = tid - 32;
            for (int c = c0; c < SCAN_CH; c += 224) cp_async16(dst + c * 16, src + c * 16);
            CP_COMMIT();
            CP_WAIT(5);
        }
        __syncthreads();  // (1) buf[t%6] ready; sa from previous step visible

        const __nv_bfloat16* Xc = buf[t % 6];

        float s = 0.f, s2 = 0.f;
        if (j < LBL) {
#pragma unroll
            for (int it = 0; it < 13; it++) {
                int i = g + 4 * it;
                if (i < LBL) {
                    float v = sa[i] * __bfloat162float(Xc[i * LBL + j]);
                    if (it & 1) s2 += v; else s += v;
                }
            }
            s += s2;
        }
        red[tid] = s;
        if (tid == 255)
            tgtE_reg += __logf(__bfloat162float(Xc[s_tg[t - 1] * LBL + s_tg[t]]));
        __syncthreads();  // (2) partials ready

        if (wid == 0) {
            const float m = s_mask[t];
            float tot0 = red[lane] + red[lane + 64] + red[lane + 128] + red[lane + 192];
            float tot1 = red[lane + 32] + red[lane + 96] + red[lane + 160] + red[lane + 224];
            float tr = __shfl_sync(0xffffffffu, tot0, 0);
            if (m == 1.0f) {
                float inv = __fdividef(1.f, tr);
                if (lane < LBL)      sa[lane]      = tot0 * inv;
                if (lane + 32 < LBL) sa[lane + 32] = tot1 * inv;
                P0 += __logf(tr);          // off critical path
            } else if (m != 0.0f) {
                float pj0 = (lane < LBL) ? (P0 + __logf(sa[lane])) : -1e30f;
                float pj1 = (lane + 32 < LBL) ? (P0 + __logf(sa[lane + 32])) : -1e30f;
                float pn0 = P0 + __logf(tot0);
                float pn1 = P0 + __logf(tot1);
                pj0 += (pn0 - pj0) * m;
                pj1 += (pn1 - pj1) * m;
                float nr = __shfl_sync(0xffffffffu, pj0, 0);
                if (lane < LBL)      sa[lane]      = __expf(pj0 - nr);
                if (lane + 32 < LBL) sa[lane + 32] = __expf(pj1 - nr);
                P0 = nr;
            }
            // m == 0: unchanged
        }
        // next iteration's barrier (1) protects sa
    }

    if (tid == 255) s_tgtE[0] = tgtE_reg;
    __syncthreads();

    if (wid == 0) {
        float sm = 0.f;
        if (lane < LBL)      sm += sa[lane];
        if (lane + 32 < LBL) sm += sa[lane + 32];
#pragma unroll
        for (int o = 16; o > 0; o >>= 1)
            sm += __shfl_xor_sync(0xffffffffu, sm, o);
        if (lane == 0) out[b] = P0 + __logf(sm) - s_tgtE[0];
    }
}

// ---------------------------------------------------------------------------
extern "C" void kernel_launch(void* const* d_in, const int* in_sizes, int n_in,
                              void* d_out, int out_size) {
    const float* input  = (const float*)d_in[0];
    const float* mask   = (const float*)d_in[1];
    const int*   target = (const int*)d_in[2];
    const float* sW     = (const float*)d_in[3];
    const float* sb     = (const float*)d_in[4];
    const float* tW     = (const float*)d_in[5];
    const float* tb     = (const float*)d_in[6];
    float* out = (float*)d_out;

    (void)in_sizes; (void)n_in; (void)out_size;

    prep_kernel<<<PREP_A_BLOCKS + PREP_W_BLOCKS, 256>>>(input, sW, sb, tW, tb);

    dim3 ggrid(NPAD / 128, MM / 128);  // (21, 128)
    gemm_exp_kernel<<<ggrid, 256>>>(mask);

    scan_kernel<<<BB, 256>>>(mask, target, out);
}

// round 10
// speedup vs baseline: 3.0847x; 1.0010x over previous
#include <cuda_runtime.h>
#include <cuda_bf16.h>
#include <cstdint>

// Problem constants
#define BB    64
#define TT    256
#define KK    256      // INPUT_SIZE
#define LBL   51       // L
#define NN    2601     // L*L
#define NPAD  2688     // 21 * 128
#define ESTR  2688     // X row stride (bf16 elems) = 5376 B
#define MM    16384    // B*T

// ---------------------------------------------------------------------------
// Device globals (no allocations allowed)
// ---------------------------------------------------------------------------
__device__ __align__(256) __nv_bfloat16 g_Abf[MM * KK];          // input, bf16
__device__ __align__(256) __nv_bfloat16 g_Wpb[NPAD * KK];        // folded W, [n][k] bf16
__device__ __align__(256) float         g_bp[NPAD];              // folded bias
__device__ __align__(256) __nv_bfloat16 g_X[(size_t)MM * ESTR];  // exp(mask*energy) (~88MB)

// ---------------------------------------------------------------------------
// Helpers (family-portable PTX only: cp.async, ldmatrix, mma.sync)
// ---------------------------------------------------------------------------
__device__ __forceinline__ uint32_t smem_u32(const void* p) {
    uint32_t a;
    asm("{ .reg .u64 t; cvta.to.shared.u64 t, %1; cvt.u32.u64 %0, t; }" : "=r"(a) : "l"(p));
    return a;
}
__device__ __forceinline__ void cp_async16(uint32_t smem, const void* g) {
    asm volatile("cp.async.cg.shared.global [%0], [%1], 16;\n" :: "r"(smem), "l"(g));
}
#define CP_COMMIT() asm volatile("cp.async.commit_group;\n" ::: "memory")
#define CP_WAIT(n)  asm volatile("cp.async.wait_group %0;\n" :: "n"(n) : "memory")

#define LDSM4(r0, r1, r2, r3, addr) \
    asm volatile("ldmatrix.sync.aligned.m8n8.x4.shared.b16 {%0,%1,%2,%3}, [%4];\n" \
                 : "=r"(r0), "=r"(r1), "=r"(r2), "=r"(r3) : "r"(addr))

#define MMA16816(c, a, b) \
    asm volatile("mma.sync.aligned.m16n8k16.row.col.f32.bf16.bf16.f32 " \
                 "{%0,%1,%2,%3}, {%4,%5,%6,%7}, {%8,%9}, {%0,%1,%2,%3};\n" \
                 : "+f"((c)[0]), "+f"((c)[1]), "+f"((c)[2]), "+f"((c)[3]) \
                 : "r"((a)[0]), "r"((a)[1]), "r"((a)[2]), "r"((a)[3]), \
                   "r"((b)[0]), "r"((b)[1]))

// ---------------------------------------------------------------------------
// Fused prep kernel.
// Blocks [0, PREP_A_BLOCKS): convert A to bf16, 8 front-batched float4/thread.
// Blocks [PREP_A_BLOCKS, +PREP_W_BLOCKS): W-fold, one (n, kb) pair per thread
// (fully parallel: 16 independent loads, one 16B store, no serial loop).
// ---------------------------------------------------------------------------
#define PREP_A_BLOCKS 512    // 512 * 256 * 8 float4 = MM*KK/4
#define PREP_W_BLOCKS 336    // 2688 n * 32 kb / 256

__global__ __launch_bounds__(256, 1) void prep_kernel(
        const float* __restrict__ A,
        const float* __restrict__ sW, const float* __restrict__ sb,
        const float* __restrict__ tW, const float* __restrict__ tb) {
    if (blockIdx.x < PREP_A_BLOCKS) {
        const size_t base = (size_t)blockIdx.x * 2048 + threadIdx.x;  // float4 index
        const float4* A4 = (const float4*)A;
        float4 v[8];
#pragma unroll
        for (int h = 0; h < 8; h++) v[h] = A4[base + h * 256];   // 8 outstanding loads
#pragma unroll
        for (int h = 0; h < 8; h++) {
            __nv_bfloat162 p0 = __floats2bfloat162_rn(v[h].x, v[h].y);
            __nv_bfloat162 p1 = __floats2bfloat162_rn(v[h].z, v[h].w);
            uint2 o;
            o.x = *(uint32_t*)&p0;
            o.y = *(uint32_t*)&p1;
            *(uint2*)&g_Abf[(base + h * 256) * 4] = o;
        }
        return;
    }
    // W-fold: idx -> (kb, n); consecutive threads share kb, walk n (coalesced tW)
    const int idx = (blockIdx.x - PREP_A_BLOCKS) * 256 + threadIdx.x;  // 0..86015
    const int kb  = idx / NPAD;        // 0..31
    const int n   = idx - kb * NPAD;   // 0..2687
    if (n < NN) {
        const int col = n % LBL;
        if (kb == 0) g_bp[n] = tb[n] + sb[col];
        float v[8], w[8];
#pragma unroll
        for (int i = 0; i < 8; i++)
            v[i] = tW[(size_t)(kb * 8 + i) * NN + n];    // 8 independent, coalesced
#pragma unroll
        for (int i = 0; i < 8; i++)
            w[i] = sW[(kb * 8 + i) * LBL + col];         // 8 independent
        __nv_bfloat162 p[4];
#pragma unroll
        for (int i = 0; i < 4; i++)
            p[i] = __floats2bfloat162_rn(v[2 * i] + w[2 * i], v[2 * i + 1] + w[2 * i + 1]);
        *(uint4*)&g_Wpb[n * KK + kb * 8] = *(uint4*)p;
    } else {
        if (kb == 0) g_bp[n] = 0.f;
        uint4 z = {0, 0, 0, 0};
        *(uint4*)&g_Wpb[n * KK + kb * 8] = z;
    }
}

// ---------------------------------------------------------------------------
// mma.sync GEMM + exp epilogue (3-stage cp.async pipeline, 1 bar per k-step)
//   X[m, n] = bf16( exp( mask[m] * (A . Wp + bp) ) )
// CTA tile 128x128, K-step 32. 8 warps: warp tile 64(m) x 32(n).
// ---------------------------------------------------------------------------
#define STG_ELEMS 136   // epilogue stage row stride in bf16 (272 B)

__global__ __launch_bounds__(256, 2) void gemm_exp_kernel(const float* __restrict__ mask) {
    __shared__ __align__(128) char sm[49152];

    const int tid = threadIdx.x;
    const int l   = tid & 31;
    const int wid = tid >> 5;
    const int wm  = wid >> 2;   // 0..1
    const int wn  = wid & 3;    // 0..3
    const int m0  = blockIdx.y * 128;
    const int n0  = blockIdx.x * 128;

    const uint32_t smBase = smem_u32(sm);

    const int a_r = (l & 7) + 8 * ((l >> 3) & 1);
    const int a_s = (l >> 4);
    uint32_t a_off[4][2];
#pragma unroll
    for (int i = 0; i < 4; i++)
#pragma unroll
        for (int ks16 = 0; ks16 < 2; ks16++) {
            int r = wm * 64 + 16 * i + a_r;
            int seg = ks16 * 2 + a_s;
            a_off[i][ks16] = r * 64 + ((seg ^ (r & 3)) << 4);
        }
    const int b_r = (l & 7) + 8 * ((l >> 4) & 1);
    const int b_s = (l >> 3) & 1;
    uint32_t b_off[2][2];
#pragma unroll
    for (int jj = 0; jj < 2; jj++)
#pragma unroll
        for (int ks16 = 0; ks16 < 2; ks16++) {
            int r = wn * 32 + 16 * jj + b_r;
            int seg = ks16 * 2 + b_s;
            b_off[jj][ks16] = r * 64 + ((seg ^ (r & 3)) << 4);
        }

    const int c0r = tid >> 2, c0s = tid & 3;
    const int c1r = (tid + 256) >> 2, c1s = tid & 3;
    const uint32_t so0 = c0r * 64 + ((c0s ^ (c0r & 3)) << 4);
    const uint32_t so1 = c1r * 64 + ((c1s ^ (c1r & 3)) << 4);

#define LOAD_STAGE(s, ks) do {                                                        \
        uint32_t bA = smBase + (s) * 16384;                                           \
        uint32_t bW = bA + 8192;                                                      \
        cp_async16(bA + so0, g_Abf + (size_t)(m0 + c0r) * KK + (ks) * 32 + c0s * 8);  \
        cp_async16(bA + so1, g_Abf + (size_t)(m0 + c1r) * KK + (ks) * 32 + c1s * 8);  \
        cp_async16(bW + so0, g_Wpb + (size_t)(n0 + c0r) * KK + (ks) * 32 + c0s * 8);  \
        cp_async16(bW + so1, g_Wpb + (size_t)(n0 + c1r) * KK + (ks) * 32 + c1s * 8);  \
        CP_COMMIT();                                                                  \
    } while (0)

    float acc[4][4][4];
#pragma unroll
    for (int i = 0; i < 4; i++)
#pragma unroll
        for (int j = 0; j < 4; j++)
#pragma unroll
            for (int q = 0; q < 4; q++) acc[i][j][q] = 0.f;

    LOAD_STAGE(0, 0);
    LOAD_STAGE(1, 1);

#pragma unroll 1
    for (int ks = 0; ks < 8; ks++) {
        if (ks < 7) { CP_WAIT(1); } else { CP_WAIT(0); }
        __syncthreads();
        if (ks + 2 < 8) LOAD_STAGE((ks + 2) % 3, ks + 2);

        const uint32_t bA = smBase + (ks % 3) * 16384;
        const uint32_t bW = bA + 8192;

#pragma unroll
        for (int ks16 = 0; ks16 < 2; ks16++) {
            uint32_t a[4][4];
            uint32_t b[4][2];
#pragma unroll
            for (int i = 0; i < 4; i++)
                LDSM4(a[i][0], a[i][1], a[i][2], a[i][3], bA + a_off[i][ks16]);
#pragma unroll
            for (int jj = 0; jj < 2; jj++)
                LDSM4(b[2 * jj][0], b[2 * jj][1], b[2 * jj + 1][0], b[2 * jj + 1][1],
                      bW + b_off[jj][ks16]);
#pragma unroll
            for (int i = 0; i < 4; i++)
#pragma unroll
                for (int j = 0; j < 4; j++)
                    MMA16816(acc[i][j], a[i], b[j]);
        }
    }
    __syncthreads();

    // Epilogue: exp(mask*(acc+bias)) -> bf16, stage via smem, coalesced write
    __nv_bfloat16* stage = (__nv_bfloat16*)sm;
    const int qr = l >> 2, qc = l & 3;

    float bj0[4], bj1[4];
#pragma unroll
    for (int j = 0; j < 4; j++) {
        int n = n0 + wn * 32 + 8 * j + 2 * qc;
        bj0[j] = g_bp[n];
        bj1[j] = g_bp[n + 1];
    }

#pragma unroll
    for (int i = 0; i < 4; i++) {
        int mlo = wm * 64 + 16 * i + qr;
        float mk_lo = mask[m0 + mlo];
        float mk_hi = mask[m0 + mlo + 8];
#pragma unroll
        for (int j = 0; j < 4; j++) {
            int nl = wn * 32 + 8 * j + 2 * qc;
            float f00 = __expf(mk_lo * (acc[i][j][0] + bj0[j]));
            float f01 = __expf(mk_lo * (acc[i][j][1] + bj1[j]));
            float f10 = __expf(mk_hi * (acc[i][j][2] + bj0[j]));
            float f11 = __expf(mk_hi * (acc[i][j][3] + bj1[j]));
            *(__nv_bfloat162*)&stage[mlo * STG_ELEMS + nl]       = __floats2bfloat162_rn(f00, f01);
            *(__nv_bfloat162*)&stage[(mlo + 8) * STG_ELEMS + nl] = __floats2bfloat162_rn(f10, f11);
        }
    }
    __syncthreads();

#pragma unroll
    for (int h = 0; h < 8; h++) {
        int c = tid + h * 256;
        int row = c >> 4;
        int seg = c & 15;
        uint4 v = *(const uint4*)&stage[row * STG_ELEMS + seg * 8];
        *(uint4*)&g_X[(size_t)(m0 + row) * ESTR + n0 + seg * 8] = v;
    }
}

// ---------------------------------------------------------------------------
// Forward-algorithm scan (bf16 X), ratio recurrence (no log/exp in chain):
//   sa_new[j] = tot[j] / tot[0],   P0 += log(tot[0])
// Binary mask fast paths (m==1 ratio, m==0 skip); exact log fallback otherwise.
// One CTA per batch element; warps 1-7 prefetch (6-buffer, lead 5).
// ---------------------------------------------------------------------------
#define SCAN_CH 326   // 16B chunks covering NN*2 = 5202 bytes

__global__ __launch_bounds__(256) void scan_kernel(const float* __restrict__ mask,
                                                   const int* __restrict__ target,
                                                   float* __restrict__ out) {
    const int b    = blockIdx.x;
    const int tid  = threadIdx.x;
    const int j    = tid & 63;
    const int g    = tid >> 6;
    const int lane = tid & 31;
    const int wid  = tid >> 5;

    __shared__ float sa[64];
    __shared__ float red[256];
    __shared__ float s_mask[TT];
    __shared__ int   s_tg[TT];
    __shared__ float s_tgtE[1];
    __shared__ __align__(16) __nv_bfloat16 buf[6][ESTR];  // 32256B

    const __nv_bfloat16* Xb = g_X + (size_t)b * TT * ESTR;

    s_mask[tid] = mask[b * TT + tid];
    s_tg[tid]   = target[b * TT + tid];

    if (wid > 0) {
        const int c0 = tid - 32;  // 0..223
#pragma unroll 1
        for (int r = 1; r <= 5; r++) {
            const char* src = (const char*)(Xb + (size_t)r * ESTR);
            uint32_t dst = smem_u32(buf[r]);
            for (int c = c0; c < SCAN_CH; c += 224) cp_async16(dst + c * 16, src + c * 16);
            CP_COMMIT();
        }
    }

    __syncthreads();  // s_tg/s_mask visible to all

    // t=0 init: sa[j] = X0[L-1,j] / X0[L-1,0]; P0 = log(X0[L-1,0])
    float P0 = 0.f, tgtE_reg = 0.f;
    if (wid == 0) {
        float v0 = (lane < LBL) ? __bfloat162float(Xb[(LBL - 1) * LBL + lane]) : 1.f;
        float v1 = (lane + 32 < LBL) ? __bfloat162float(Xb[(LBL - 1) * LBL + lane + 32]) : 1.f;
        float vr = __shfl_sync(0xffffffffu, v0, 0);
        float inv = __fdividef(1.f, vr);
        if (lane < LBL)      sa[lane]      = v0 * inv;
        if (lane + 32 < LBL) sa[lane + 32] = v1 * inv;
        P0 = __logf(vr);
    }
    if (tid == 255)
        tgtE_reg = __logf(__bfloat162float(Xb[(LBL - 1) * LBL + s_tg[0]]));
    // (sa visibility guaranteed by the first loop barrier)

#pragma unroll 1
    for (int t = 1; t < TT; t++) {
        if (wid > 0) {
            const int tf = (t + 5 < TT) ? (t + 5) : (TT - 1);
            const char* src = (const char*)(Xb + (size_t)tf * ESTR);
            uint32_t dst = smem_u32(buf[(t + 5) % 6]);
            const int c0 = tid - 32;
            for (int c = c0; c < SCAN_CH; c += 224) cp_async16(dst + c * 16, src + c * 16);
            CP_COMMIT();
            CP_WAIT(5);
        }
        __syncthreads();  // (1) buf[t%6] ready; sa from previous step visible

        const __nv_bfloat16* Xc = buf[t % 6];

        float s = 0.f, s2 = 0.f;
        if (j < LBL) {
#pragma unroll
            for (int it = 0; it < 13; it++) {
                int i = g + 4 * it;
                if (i < LBL) {
                    float v = sa[i] * __bfloat162float(Xc[i * LBL + j]);
                    if (it & 1) s2 += v; else s += v;
                }
            }
            s += s2;
        }
        red[tid] = s;
        if (tid == 255)
            tgtE_reg += __logf(__bfloat162float(Xc[s_tg[t - 1] * LBL + s_tg[t]]));
        __syncthreads();  // (2) partials ready

        if (wid == 0) {
            const float m = s_mask[t];
            float tot0 = red[lane] + red[lane + 64] + red[lane + 128] + red[lane + 192];
            float tot1 = red[lane + 32] + red[lane + 96] + red[lane + 160] + red[lane + 224];
            float tr = __shfl_sync(0xffffffffu, tot0, 0);
            if (m == 1.0f) {
                float inv = __fdividef(1.f, tr);
                if (lane < LBL)      sa[lane]      = tot0 * inv;
                if (lane + 32 < LBL) sa[lane + 32] = tot1 * inv;
                P0 += __logf(tr);          // off critical path
            } else if (m != 0.0f) {
                float pj0 = (lane < LBL) ? (P0 + __logf(sa[lane])) : -1e30f;
                float pj1 = (lane + 32 < LBL) ? (P0 + __logf(sa[lane + 32])) : -1e30f;
                float pn0 = P0 + __logf(tot0);
                float pn1 = P0 + __logf(tot1);
                pj0 += (pn0 - pj0) * m;
                pj1 += (pn1 - pj1) * m;
                float nr = __shfl_sync(0xffffffffu, pj0, 0);
                if (lane < LBL)      sa[lane]      = __expf(pj0 - nr);
                if (lane + 32 < LBL) sa[lane + 32] = __expf(pj1 - nr);
                P0 = nr;
            }
            // m == 0: unchanged
        }
        // next iteration's barrier (1) protects sa
    }

    if (tid == 255) s_tgtE[0] = tgtE_reg;
    __syncthreads();

    if (wid == 0) {
        float sm = 0.f;
        if (lane < LBL)      sm += sa[lane];
        if (lane + 32 < LBL) sm += sa[lane + 32];
#pragma unroll
        for (int o = 16; o > 0; o >>= 1)
            sm += __shfl_xor_sync(0xffffffffu, sm, o);
        if (lane == 0) out[b] = P0 + __logf(sm) - s_tgtE[0];
    }
}

// ---------------------------------------------------------------------------
extern "C" void kernel_launch(void* const* d_in, const int* in_sizes, int n_in,
                              void* d_out, int out_size) {
    const float* input  = (const float*)d_in[0];
    const float* mask   = (const float*)d_in[1];
    const int*   target = (const int*)d_in[2];
    const float* sW     = (const float*)d_in[3];
    const float* sb     = (const float*)d_in[4];
    const float* tW     = (const float*)d_in[5];
    const float* tb     = (const float*)d_in[6];
    float* out = (float*)d_out;

    (void)in_sizes; (void)n_in; (void)out_size;

    prep_kernel<<<PREP_A_BLOCKS + PREP_W_BLOCKS, 256>>>(input, sW, sb, tW, tb);

    dim3 ggrid(NPAD / 128, MM / 128);  // (21, 128)
    gemm_exp_kernel<<<ggrid, 256>>>(mask);

    scan_kernel<<<BB, 256>>>(mask, target, out);
}

// round 11
// speedup vs baseline: 3.0856x; 1.0003x over previous
#include <cuda_runtime.h>
#include <cuda_bf16.h>
#include <cstdint>

// Problem constants
#define BB    64
#define TT    256
#define KK    256      // INPUT_SIZE
#define LBL   51       // L
#define NN    2601     // L*L
#define NPAD  2688     // 21 * 128
#define ESTR  2688     // X row stride (bf16 elems) = 5376 B
#define MM    16384    // B*T

// ---------------------------------------------------------------------------
// Device globals (no allocations allowed)
// ---------------------------------------------------------------------------
__device__ __align__(256) __nv_bfloat16 g_Abf[MM * KK];          // input, bf16
__device__ __align__(256) __nv_bfloat16 g_Wpb[NPAD * KK];        // folded W, [n][k] bf16
__device__ __align__(256) float         g_bp[NPAD];              // folded bias
__device__ __align__(256) __nv_bfloat16 g_X[(size_t)MM * ESTR];  // exp(mask*energy) (~88MB)

// ---------------------------------------------------------------------------
// Helpers (family-portable PTX only: cp.async, ldmatrix, mma.sync)
// ---------------------------------------------------------------------------
__device__ __forceinline__ uint32_t smem_u32(const void* p) {
    uint32_t a;
    asm("{ .reg .u64 t; cvta.to.shared.u64 t, %1; cvt.u32.u64 %0, t; }" : "=r"(a) : "l"(p));
    return a;
}
__device__ __forceinline__ void cp_async16(uint32_t smem, const void* g) {
    asm volatile("cp.async.cg.shared.global [%0], [%1], 16;\n" :: "r"(smem), "l"(g));
}
#define CP_COMMIT() asm volatile("cp.async.commit_group;\n" ::: "memory")
#define CP_WAIT(n)  asm volatile("cp.async.wait_group %0;\n" :: "n"(n) : "memory")

#define LDSM4(r0, r1, r2, r3, addr) \
    asm volatile("ldmatrix.sync.aligned.m8n8.x4.shared.b16 {%0,%1,%2,%3}, [%4];\n" \
                 : "=r"(r0), "=r"(r1), "=r"(r2), "=r"(r3) : "r"(addr))

#define MMA16816(c, a, b) \
    asm volatile("mma.sync.aligned.m16n8k16.row.col.f32.bf16.bf16.f32 " \
                 "{%0,%1,%2,%3}, {%4,%5,%6,%7}, {%8,%9}, {%0,%1,%2,%3};\n" \
                 : "+f"((c)[0]), "+f"((c)[1]), "+f"((c)[2]), "+f"((c)[3]) \
                 : "r"((a)[0]), "r"((a)[1]), "r"((a)[2]), "r"((a)[3]), \
                   "r"((b)[0]), "r"((b)[1]))

// ---------------------------------------------------------------------------
// Fused prep kernel.
// Blocks [0, PREP_A_BLOCKS): convert A to bf16, 8 front-batched float4/thread.
// Blocks [PREP_A_BLOCKS, +PREP_W_BLOCKS): W-fold, one (n, kb) pair per thread
// (fully parallel: 16 independent loads, one 16B store, no serial loop).
// ---------------------------------------------------------------------------
#define PREP_A_BLOCKS 512    // 512 * 256 * 8 float4 = MM*KK/4
#define PREP_W_BLOCKS 336    // 2688 n * 32 kb / 256

__global__ __launch_bounds__(256, 1) void prep_kernel(
        const float* __restrict__ A,
        const float* __restrict__ sW, const float* __restrict__ sb,
        const float* __restrict__ tW, const float* __restrict__ tb) {
    if (blockIdx.x < PREP_A_BLOCKS) {
        const size_t base = (size_t)blockIdx.x * 2048 + threadIdx.x;  // float4 index
        const float4* A4 = (const float4*)A;
        float4 v[8];
#pragma unroll
        for (int h = 0; h < 8; h++) v[h] = A4[base + h * 256];   // 8 outstanding loads
#pragma unroll
        for (int h = 0; h < 8; h++) {
            __nv_bfloat162 p0 = __floats2bfloat162_rn(v[h].x, v[h].y);
            __nv_bfloat162 p1 = __floats2bfloat162_rn(v[h].z, v[h].w);
            uint2 o;
            o.x = *(uint32_t*)&p0;
            o.y = *(uint32_t*)&p1;
            *(uint2*)&g_Abf[(base + h * 256) * 4] = o;
        }
        return;
    }
    // W-fold: idx -> (kb, n); consecutive threads share kb, walk n (coalesced tW)
    const int idx = (blockIdx.x - PREP_A_BLOCKS) * 256 + threadIdx.x;  // 0..86015
    const int kb  = idx / NPAD;        // 0..31
    const int n   = idx - kb * NPAD;   // 0..2687
    if (n < NN) {
        const int col = n % LBL;
        if (kb == 0) g_bp[n] = tb[n] + sb[col];
        float v[8], w[8];
#pragma unroll
        for (int i = 0; i < 8; i++)
            v[i] = tW[(size_t)(kb * 8 + i) * NN + n];    // 8 independent, coalesced
#pragma unroll
        for (int i = 0; i < 8; i++)
            w[i] = sW[(kb * 8 + i) * LBL + col];         // 8 independent
        __nv_bfloat162 p[4];
#pragma unroll
        for (int i = 0; i < 4; i++)
            p[i] = __floats2bfloat162_rn(v[2 * i] + w[2 * i], v[2 * i + 1] + w[2 * i + 1]);
        *(uint4*)&g_Wpb[n * KK + kb * 8] = *(uint4*)p;
    } else {
        if (kb == 0) g_bp[n] = 0.f;
        uint4 z = {0, 0, 0, 0};
        *(uint4*)&g_Wpb[n * KK + kb * 8] = z;
    }
}

// ---------------------------------------------------------------------------
// mma.sync GEMM + exp epilogue (3-stage cp.async pipeline, 1 bar per k-step)
//   X[m, n] = bf16( exp( mask[m] * (A . Wp + bp) ) )
// CTA tile 128x128, K-step 32. 8 warps: warp tile 64(m) x 32(n).
// ---------------------------------------------------------------------------
#define STG_ELEMS 136   // epilogue stage row stride in bf16 (272 B)

__global__ __launch_bounds__(256, 2) void gemm_exp_kernel(const float* __restrict__ mask) {
    __shared__ __align__(128) char sm[49152];

    const int tid = threadIdx.x;
    const int l   = tid & 31;
    const int wid = tid >> 5;
    const int wm  = wid >> 2;   // 0..1
    const int wn  = wid & 3;    // 0..3
    const int m0  = blockIdx.y * 128;
    const int n0  = blockIdx.x * 128;

    const uint32_t smBase = smem_u32(sm);

    const int a_r = (l & 7) + 8 * ((l >> 3) & 1);
    const int a_s = (l >> 4);
    uint32_t a_off[4][2];
#pragma unroll
    for (int i = 0; i < 4; i++)
#pragma unroll
        for (int ks16 = 0; ks16 < 2; ks16++) {
            int r = wm * 64 + 16 * i + a_r;
            int seg = ks16 * 2 + a_s;
            a_off[i][ks16] = r * 64 + ((seg ^ (r & 3)) << 4);
        }
    const int b_r = (l & 7) + 8 * ((l >> 4) & 1);
    const int b_s = (l >> 3) & 1;
    uint32_t b_off[2][2];
#pragma unroll
    for (int jj = 0; jj < 2; jj++)
#pragma unroll
        for (int ks16 = 0; ks16 < 2; ks16++) {
            int r = wn * 32 + 16 * jj + b_r;
            int seg = ks16 * 2 + b_s;
            b_off[jj][ks16] = r * 64 + ((seg ^ (r & 3)) << 4);
        }

    const int c0r = tid >> 2, c0s = tid & 3;
    const int c1r = (tid + 256) >> 2, c1s = tid & 3;
    const uint32_t so0 = c0r * 64 + ((c0s ^ (c0r & 3)) << 4);
    const uint32_t so1 = c1r * 64 + ((c1s ^ (c1r & 3)) << 4);

#define LOAD_STAGE(s, ks) do {                                                        \
        uint32_t bA = smBase + (s) * 16384;                                           \
        uint32_t bW = bA + 8192;                                                      \
        cp_async16(bA + so0, g_Abf + (size_t)(m0 + c0r) * KK + (ks) * 32 + c0s * 8);  \
        cp_async16(bA + so1, g_Abf + (size_t)(m0 + c1r) * KK + (ks) * 32 + c1s * 8);  \
        cp_async16(bW + so0, g_Wpb + (size_t)(n0 + c0r) * KK + (ks) * 32 + c0s * 8);  \
        cp_async16(bW + so1, g_Wpb + (size_t)(n0 + c1r) * KK + (ks) * 32 + c1s * 8);  \
        CP_COMMIT();                                                                  \
    } while (0)

    float acc[4][4][4];
#pragma unroll
    for (int i = 0; i < 4; i++)
#pragma unroll
        for (int j = 0; j < 4; j++)
#pragma unroll
            for (int q = 0; q < 4; q++) acc[i][j][q] = 0.f;

    LOAD_STAGE(0, 0);
    LOAD_STAGE(1, 1);

#pragma unroll 1
    for (int ks = 0; ks < 8; ks++) {
        if (ks < 7) { CP_WAIT(1); } else { CP_WAIT(0); }
        __syncthreads();
        if (ks + 2 < 8) LOAD_STAGE((ks + 2) % 3, ks + 2);

        const uint32_t bA = smBase + (ks % 3) * 16384;
        const uint32_t bW = bA + 8192;

#pragma unroll
        for (int ks16 = 0; ks16 < 2; ks16++) {
            uint32_t a[4][4];
            uint32_t b[4][2];
#pragma unroll
            for (int i = 0; i < 4; i++)
                LDSM4(a[i][0], a[i][1], a[i][2], a[i][3], bA + a_off[i][ks16]);
#pragma unroll
            for (int jj = 0; jj < 2; jj++)
                LDSM4(b[2 * jj][0], b[2 * jj][1], b[2 * jj + 1][0], b[2 * jj + 1][1],
                      bW + b_off[jj][ks16]);
#pragma unroll
            for (int i = 0; i < 4; i++)
#pragma unroll
                for (int j = 0; j < 4; j++)
                    MMA16816(acc[i][j], a[i], b[j]);
        }
    }
    __syncthreads();

    // Epilogue: exp(mask*(acc+bias)) -> bf16, stage via smem, coalesced write
    __nv_bfloat16* stage = (__nv_bfloat16*)sm;
    const int qr = l >> 2, qc = l & 3;

    float bj0[4], bj1[4];
#pragma unroll
    for (int j = 0; j < 4; j++) {
        int n = n0 + wn * 32 + 8 * j + 2 * qc;
        bj0[j] = g_bp[n];
        bj1[j] = g_bp[n + 1];
    }

#pragma unroll
    for (int i = 0; i < 4; i++) {
        int mlo = wm * 64 + 16 * i + qr;
        float mk_lo = mask[m0 + mlo];
        float mk_hi = mask[m0 + mlo + 8];
#pragma unroll
        for (int j = 0; j < 4; j++) {
            int nl = wn * 32 + 8 * j + 2 * qc;
            float f00 = __expf(mk_lo * (acc[i][j][0] + bj0[j]));
            float f01 = __expf(mk_lo * (acc[i][j][1] + bj1[j]));
            float f10 = __expf(mk_hi * (acc[i][j][2] + bj0[j]));
            float f11 = __expf(mk_hi * (acc[i][j][3] + bj1[j]));
            *(__nv_bfloat162*)&stage[mlo * STG_ELEMS + nl]       = __floats2bfloat162_rn(f00, f01);
            *(__nv_bfloat162*)&stage[(mlo + 8) * STG_ELEMS + nl] = __floats2bfloat162_rn(f10, f11);
        }
    }
    __syncthreads();

#pragma unroll
    for (int h = 0; h < 8; h++) {
        int c = tid + h * 256;
        int row = c >> 4;
        int seg = c & 15;
        uint4 v = *(const uint4*)&stage[row * STG_ELEMS + seg * 8];
        *(uint4*)&g_X[(size_t)(m0 + row) * ESTR + n0 + seg * 8] = v;
    }
}

// ---------------------------------------------------------------------------
// Forward-algorithm scan (bf16 X), ratio recurrence (no log/exp in chain):
//   sa_new[j] = tot[j] / tot[0],   P0 += log(tot[0])
// Binary mask fast paths (m==1 ratio, m==0 skip); exact log fallback otherwise.
// One CTA per batch element; warps 1-7 prefetch (6-buffer, lead 5).
// ---------------------------------------------------------------------------
#define SCAN_CH 326   // 16B chunks covering NN*2 = 5202 bytes

__global__ __launch_bounds__(256) void scan_kernel(const float* __restrict__ mask,
                                                   const int* __restrict__ target,
                                                   float* __restrict__ out) {
    const int b    = blockIdx.x;
    const int tid  = threadIdx.x;
    const int j    = tid & 63;
    const int g    = tid >> 6;
    const int lane = tid & 31;
    const int wid  = tid >> 5;

    __shared__ float sa[64];
    __shared__ float red[256];
    __shared__ float s_mask[TT];
    __shared__ int   s_tg[TT];
    __shared__ float s_tgtE[1];
    __shared__ __align__(16) __nv_bfloat16 buf[6][ESTR];  // 32256B

    const __nv_bfloat16* Xb = g_X + (size_t)b * TT * ESTR;

    s_mask[tid] = mask[b * TT + tid];
    s_tg[tid]   = target[b * TT + tid];

    if (wid > 0) {
        const int c0 = tid - 32;  // 0..223
#pragma unroll 1
        for (int r = 1; r <= 5; r++) {
            const char* src = (const char*)(Xb + (size_t)r * ESTR);
            uint32_t dst = smem_u32(buf[r]);
            for (int c = c0; c < SCAN_CH; c += 224) cp_async16(dst + c * 16, src + c * 16);
            CP_COMMIT();
        }
    }

    __syncthreads();  // s_tg/s_mask visible to all

    // t=0 init: sa[j] = X0[L-1,j] / X0[L-1,0]; P0 = log(X0[L-1,0])
    float P0 = 0.f, tgtE_reg = 0.f;
    if (wid == 0) {
        float v0 = (lane < LBL) ? __bfloat162float(Xb[(LBL - 1) * LBL + lane]) : 1.f;
        float v1 = (lane + 32 < LBL) ? __bfloat162float(Xb[(LBL - 1) * LBL + lane + 32]) : 1.f;
        float vr = __shfl_sync(0xffffffffu, v0, 0);
        float inv = __fdividef(1.f, vr);
        if (lane < LBL)      sa[lane]      = v0 * inv;
        if (lane + 32 < LBL) sa[lane + 32] = v1 * inv;
        P0 = __logf(vr);
    }
    if (tid == 255)
        tgtE_reg = __logf(__bfloat162float(Xb[(LBL - 1) * LBL + s_tg[0]]));
    // (sa visibility guaranteed by the first loop barrier)

#pragma unroll 1
    for (int t = 1; t < TT; t++) {
        if (wid > 0) {
            const int tf = (t + 5 < TT) ? (t + 5) : (TT - 1);
            const char* src = (const char*)(Xb + (size_t)tf * ESTR);
            uint32_t dst = smem_u32(buf[(t + 5) % 6]);
            const int c0 = tid - 32;
            for (int c = c0; c < SCAN_CH; c += 224) cp_async16(dst + c * 16, src + c * 16);
            CP_COMMIT();
            CP_WAIT(5);
        }
        __syncthreads();  // (1) buf[t%6] ready; sa from previous step visible

        const __nv_bfloat16* Xc = buf[t % 6];

        float s = 0.f, s2 = 0.f;
        if (j < LBL) {
#pragma unroll
            for (int it = 0; it < 13; it++) {
                int i = g + 4 * it;
                if (i < LBL) {
                    float v = sa[i] * __bfloat162float(Xc[i * LBL + j]);
                    if (it & 1) s2 += v; else s += v;
                }
            }
            s += s2;
        }
        red[tid] = s;
        if (tid == 255)
            tgtE_reg += __logf(__bfloat162float(Xc[s_tg[t - 1] * LBL + s_tg[t]]));
        __syncthreads();  // (2) partials ready

        if (wid == 0) {
            const float m = s_mask[t];
            float tot0 = red[lane] + red[lane + 64] + red[lane + 128] + red[lane + 192];
            float tot1 = red[lane + 32] + red[lane + 96] + red[lane + 160] + red[lane + 224];
            float tr = __shfl_sync(0xffffffffu, tot0, 0);
            if (m == 1.0f) {
                float inv = __fdividef(1.f, tr);
                if (lane < LBL)      sa[lane]      = tot0 * inv;
                if (lane + 32 < LBL) sa[lane + 32] = tot1 * inv;
                P0 += __logf(tr);          // off critical path
            } else if (m != 0.0f) {
                float pj0 = (lane < LBL) ? (P0 + __logf(sa[lane])) : -1e30f;
                float pj1 = (lane + 32 < LBL) ? (P0 + __logf(sa[lane + 32])) : -1e30f;
                float pn0 = P0 + __logf(tot0);
                float pn1 = P0 + __logf(tot1);
                pj0 += (pn0 - pj0) * m;
                pj1 += (pn1 - pj1) * m;
                float nr = __shfl_sync(0xffffffffu, pj0, 0);
                if (lane < LBL)      sa[lane]      = __expf(pj0 - nr);
                if (lane + 32 < LBL) sa[lane + 32] = __expf(pj1 - nr);
                P0 = nr;
            }
            // m == 0: unchanged
        }
        // next iteration's barrier (1) protects sa
    }

    if (tid == 255) s_tgtE[0] = tgtE_reg;
    __syncthreads();

    if (wid == 0) {
        float sm = 0.f;
        if (lane < LBL)      sm += sa[lane];
        if (lane + 32 < LBL) sm += sa[lane + 32];
#pragma unroll
        for (int o = 16; o > 0; o >>= 1)
            sm += __shfl_xor_sync(0xffffffffu, sm, o);
        if (lane == 0) out[b] = P0 + __logf(sm) - s_tgtE[0];
    }
}

// ---------------------------------------------------------------------------
extern "C" void kernel_launch(void* const* d_in, const int* in_sizes, int n_in,
                              void* d_out, int out_size) {
    const float* input  = (const float*)d_in[0];
    const float* mask   = (const float*)d_in[1];
    const int*   target = (const int*)d_in[2];
    const float* sW     = (const float*)d_in[3];
    const float* sb     = (const float*)d_in[4];
    const float* tW     = (const float*)d_in[5];
    const float* tb     = (const float*)d_in[6];
    float* out = (float*)d_out;

    (void)in_sizes; (void)n_in; (void)out_size;

    prep_kernel<<<PREP_A_BLOCKS + PREP_W_BLOCKS, 256>>>(input, sW, sb, tW, tb);

    dim3 ggrid(NPAD / 128, MM / 128);  // (21, 128)
    gemm_exp_kernel<<<ggrid, 256>>>(mask);

    scan_kernel<<<BB, 256>>>(mask, target, out);
}

// round 12
// speedup vs baseline: 3.0893x; 1.0012x over previous
#include <cuda_runtime.h>
#include <cuda_bf16.h>
#include <cstdint>

// Problem constants
#define BB    64
#define TT    256
#define KK    256      // INPUT_SIZE
#define LBL   51       // L
#define NN    2601     // L*L
#define NPAD  2688     // 21 * 128
#define ESTR  2688     // X row stride (bf16 elems) = 5376 B
#define MM    16384    // B*T

// ---------------------------------------------------------------------------
// Device globals (no allocations allowed)
// ---------------------------------------------------------------------------
__device__ __align__(256) __nv_bfloat16 g_Abf[MM * KK];          // input, bf16
__device__ __align__(256) __nv_bfloat16 g_Wpb[NPAD * KK];        // folded W, [n][k] bf16
__device__ __align__(256) float         g_bp[NPAD];              // folded bias
__device__ __align__(256) __nv_bfloat16 g_X[(size_t)MM * ESTR];  // exp(mask*energy) (~88MB)

// ---------------------------------------------------------------------------
// Helpers (family-portable PTX only: cp.async, ldmatrix, mma.sync)
// ---------------------------------------------------------------------------
__device__ __forceinline__ uint32_t smem_u32(const void* p) {
    uint32_t a;
    asm("{ .reg .u64 t; cvta.to.shared.u64 t, %1; cvt.u32.u64 %0, t; }" : "=r"(a) : "l"(p));
    return a;
}
__device__ __forceinline__ void cp_async16(uint32_t smem, const void* g) {
    asm volatile("cp.async.cg.shared.global [%0], [%1], 16;\n" :: "r"(smem), "l"(g));
}
#define CP_COMMIT() asm volatile("cp.async.commit_group;\n" ::: "memory")
#define CP_WAIT(n)  asm volatile("cp.async.wait_group %0;\n" :: "n"(n) : "memory")

#define LDSM4(r0, r1, r2, r3, addr) \
    asm volatile("ldmatrix.sync.aligned.m8n8.x4.shared.b16 {%0,%1,%2,%3}, [%4];\n" \
                 : "=r"(r0), "=r"(r1), "=r"(r2), "=r"(r3) : "r"(addr))

#define MMA16816(c, a, b) \
    asm volatile("mma.sync.aligned.m16n8k16.row.col.f32.bf16.bf16.f32 " \
                 "{%0,%1,%2,%3}, {%4,%5,%6,%7}, {%8,%9}, {%0,%1,%2,%3};\n" \
                 : "+f"((c)[0]), "+f"((c)[1]), "+f"((c)[2]), "+f"((c)[3]) \
                 : "r"((a)[0]), "r"((a)[1]), "r"((a)[2]), "r"((a)[3]), \
                   "r"((b)[0]), "r"((b)[1]))

// ---------------------------------------------------------------------------
// Fused prep kernel.
// Blocks [0, PREP_A_BLOCKS): convert A to bf16, 8 front-batched float4/thread.
// Blocks [PREP_A_BLOCKS, +PREP_W_BLOCKS): W-fold, one (n, kb) pair per thread
// (fully parallel: 16 independent loads, one 16B store, no serial loop).
// ---------------------------------------------------------------------------
#define PREP_A_BLOCKS 512    // 512 * 256 * 8 float4 = MM*KK/4
#define PREP_W_BLOCKS 336    // 2688 n * 32 kb / 256

__global__ __launch_bounds__(256, 1) void prep_kernel(
        const float* __restrict__ A,
        const float* __restrict__ sW, const float* __restrict__ sb,
        const float* __restrict__ tW, const float* __restrict__ tb) {
    if (blockIdx.x < PREP_A_BLOCKS) {
        const size_t base = (size_t)blockIdx.x * 2048 + threadIdx.x;  // float4 index
        const float4* A4 = (const float4*)A;
        float4 v[8];
#pragma unroll
        for (int h = 0; h < 8; h++) v[h] = A4[base + h * 256];   // 8 outstanding loads
#pragma unroll
        for (int h = 0; h < 8; h++) {
            __nv_bfloat162 p0 = __floats2bfloat162_rn(v[h].x, v[h].y);
            __nv_bfloat162 p1 = __floats2bfloat162_rn(v[h].z, v[h].w);
            uint2 o;
            o.x = *(uint32_t*)&p0;
            o.y = *(uint32_t*)&p1;
            *(uint2*)&g_Abf[(base + h * 256) * 4] = o;
        }
        return;
    }
    // W-fold: idx -> (kb, n); consecutive threads share kb, walk n (coalesced tW)
    const int idx = (blockIdx.x - PREP_A_BLOCKS) * 256 + threadIdx.x;  // 0..86015
    const int kb  = idx / NPAD;        // 0..31
    const int n   = idx - kb * NPAD;   // 0..2687
    if (n < NN) {
        const int col = n % LBL;
        if (kb == 0) g_bp[n] = tb[n] + sb[col];
        float v[8], w[8];
#pragma unroll
        for (int i = 0; i < 8; i++)
            v[i] = tW[(size_t)(kb * 8 + i) * NN + n];    // 8 independent, coalesced
#pragma unroll
        for (int i = 0; i < 8; i++)
            w[i] = sW[(kb * 8 + i) * LBL + col];         // 8 independent
        __nv_bfloat162 p[4];
#pragma unroll
        for (int i = 0; i < 4; i++)
            p[i] = __floats2bfloat162_rn(v[2 * i] + w[2 * i], v[2 * i + 1] + w[2 * i + 1]);
        *(uint4*)&g_Wpb[n * KK + kb * 8] = *(uint4*)p;
    } else {
        if (kb == 0) g_bp[n] = 0.f;
        uint4 z = {0, 0, 0, 0};
        *(uint4*)&g_Wpb[n * KK + kb * 8] = z;
    }
}

// ---------------------------------------------------------------------------
// mma.sync GEMM + exp epilogue (3-stage cp.async pipeline, 1 bar per k-step)
//   X[m, n] = bf16( exp( mask[m] * (A . Wp + bp) ) )
// CTA tile 128x128, K-step 32. 8 warps: warp tile 64(m) x 32(n).
// ---------------------------------------------------------------------------
#define STG_ELEMS 136   // epilogue stage row stride in bf16 (272 B)

__global__ __launch_bounds__(256, 2) void gemm_exp_kernel(const float* __restrict__ mask) {
    __shared__ __align__(128) char sm[49152];

    const int tid = threadIdx.x;
    const int l   = tid & 31;
    const int wid = tid >> 5;
    const int wm  = wid >> 2;   // 0..1
    const int wn  = wid & 3;    // 0..3
    const int m0  = blockIdx.y * 128;
    const int n0  = blockIdx.x * 128;

    const uint32_t smBase = smem_u32(sm);

    const int a_r = (l & 7) + 8 * ((l >> 3) & 1);
    const int a_s = (l >> 4);
    uint32_t a_off[4][2];
#pragma unroll
    for (int i = 0; i < 4; i++)
#pragma unroll
        for (int ks16 = 0; ks16 < 2; ks16++) {
            int r = wm * 64 + 16 * i + a_r;
            int seg = ks16 * 2 + a_s;
            a_off[i][ks16] = r * 64 + ((seg ^ (r & 3)) << 4);
        }
    const int b_r = (l & 7) + 8 * ((l >> 4) & 1);
    const int b_s = (l >> 3) & 1;
    uint32_t b_off[2][2];
#pragma unroll
    for (int jj = 0; jj < 2; jj++)
#pragma unroll
        for (int ks16 = 0; ks16 < 2; ks16++) {
            int r = wn * 32 + 16 * jj + b_r;
            int seg = ks16 * 2 + b_s;
            b_off[jj][ks16] = r * 64 + ((seg ^ (r & 3)) << 4);
        }

    const int c0r = tid >> 2, c0s = tid & 3;
    const int c1r = (tid + 256) >> 2, c1s = tid & 3;
    const uint32_t so0 = c0r * 64 + ((c0s ^ (c0r & 3)) << 4);
    const uint32_t so1 = c1r * 64 + ((c1s ^ (c1r & 3)) << 4);

#define LOAD_STAGE(s, ks) do {                                                        \
        uint32_t bA = smBase + (s) * 16384;                                           \
        uint32_t bW = bA + 8192;                                                      \
        cp_async16(bA + so0, g_Abf + (size_t)(m0 + c0r) * KK + (ks) * 32 + c0s * 8);  \
        cp_async16(bA + so1, g_Abf + (size_t)(m0 + c1r) * KK + (ks) * 32 + c1s * 8);  \
        cp_async16(bW + so0, g_Wpb + (size_t)(n0 + c0r) * KK + (ks) * 32 + c0s * 8);  \
        cp_async16(bW + so1, g_Wpb + (size_t)(n0 + c1r) * KK + (ks) * 32 + c1s * 8);  \
        CP_COMMIT();                                                                  \
    } while (0)

    float acc[4][4][4];
#pragma unroll
    for (int i = 0; i < 4; i++)
#pragma unroll
        for (int j = 0; j < 4; j++)
#pragma unroll
            for (int q = 0; q < 4; q++) acc[i][j][q] = 0.f;

    LOAD_STAGE(0, 0);
    LOAD_STAGE(1, 1);

#pragma unroll 1
    for (int ks = 0; ks < 8; ks++) {
        if (ks < 7) { CP_WAIT(1); } else { CP_WAIT(0); }
        __syncthreads();
        if (ks + 2 < 8) LOAD_STAGE((ks + 2) % 3, ks + 2);

        const uint32_t bA = smBase + (ks % 3) * 16384;
        const uint32_t bW = bA + 8192;

#pragma unroll
        for (int ks16 = 0; ks16 < 2; ks16++) {
            uint32_t a[4][4];
            uint32_t b[4][2];
#pragma unroll
            for (int i = 0; i < 4; i++)
                LDSM4(a[i][0], a[i][1], a[i][2], a[i][3], bA + a_off[i][ks16]);
#pragma unroll
            for (int jj = 0; jj < 2; jj++)
                LDSM4(b[2 * jj][0], b[2 * jj][1], b[2 * jj + 1][0], b[2 * jj + 1][1],
                      bW + b_off[jj][ks16]);
#pragma unroll
            for (int i = 0; i < 4; i++)
#pragma unroll
                for (int j = 0; j < 4; j++)
                    MMA16816(acc[i][j], a[i], b[j]);
        }
    }
    __syncthreads();

    // Epilogue: exp(mask*(acc+bias)) -> bf16, stage via smem, coalesced write
    __nv_bfloat16* stage = (__nv_bfloat16*)sm;
    const int qr = l >> 2, qc = l & 3;

    float bj0[4], bj1[4];
#pragma unroll
    for (int j = 0; j < 4; j++) {
        int n = n0 + wn * 32 + 8 * j + 2 * qc;
        bj0[j] = g_bp[n];
        bj1[j] = g_bp[n + 1];
    }

#pragma unroll
    for (int i = 0; i < 4; i++) {
        int mlo = wm * 64 + 16 * i + qr;
        float mk_lo = mask[m0 + mlo];
        float mk_hi = mask[m0 + mlo + 8];
#pragma unroll
        for (int j = 0; j < 4; j++) {
            int nl = wn * 32 + 8 * j + 2 * qc;
            float f00 = __expf(mk_lo * (acc[i][j][0] + bj0[j]));
            float f01 = __expf(mk_lo * (acc[i][j][1] + bj1[j]));
            float f10 = __expf(mk_hi * (acc[i][j][2] + bj0[j]));
            float f11 = __expf(mk_hi * (acc[i][j][3] + bj1[j]));
            *(__nv_bfloat162*)&stage[mlo * STG_ELEMS + nl]       = __floats2bfloat162_rn(f00, f01);
            *(__nv_bfloat162*)&stage[(mlo + 8) * STG_ELEMS + nl] = __floats2bfloat162_rn(f10, f11);
        }
    }
    __syncthreads();

#pragma unroll
    for (int h = 0; h < 8; h++) {
        int c = tid + h * 256;
        int row = c >> 4;
        int seg = c & 15;
        uint4 v = *(const uint4*)&stage[row * STG_ELEMS + seg * 8];
        *(uint4*)&g_X[(size_t)(m0 + row) * ESTR + n0 + seg * 8] = v;
    }
}

// ---------------------------------------------------------------------------
// Forward-algorithm scan (bf16 X), ratio recurrence (no log/exp in chain):
//   sa_new[j] = tot[j] / tot[0],   P0 += log(tot[0])
// Binary mask fast paths (m==1 ratio, m==0 skip); exact log fallback otherwise.
// One CTA per batch element; warps 1-7 prefetch (6-buffer, lead 5).
// ---------------------------------------------------------------------------
#define SCAN_CH 326   // 16B chunks covering NN*2 = 5202 bytes

__global__ __launch_bounds__(256) void scan_kernel(const float* __restrict__ mask,
                                                   const int* __restrict__ target,
                                                   float* __restrict__ out) {
    const int b    = blockIdx.x;
    const int tid  = threadIdx.x;
    const int j    = tid & 63;
    const int g    = tid >> 6;
    const int lane = tid & 31;
    const int wid  = tid >> 5;

    __shared__ float sa[64];
    __shared__ float red[256];
    __shared__ float s_mask[TT];
    __shared__ int   s_tg[TT];
    __shared__ float s_tgtE[1];
    __shared__ __align__(16) __nv_bfloat16 buf[6][ESTR];  // 32256B

    const __nv_bfloat16* Xb = g_X + (size_t)b * TT * ESTR;

    s_mask[tid] = mask[b * TT + tid];
    s_tg[tid]   = target[b * TT + tid];

    if (wid > 0) {
        const int c0 = tid - 32;  // 0..223
#pragma unroll 1
        for (int r = 1; r <= 5; r++) {
            const char* src = (const char*)(Xb + (size_t)r * ESTR);
            uint32_t dst = smem_u32(buf[r]);
            for (int c = c0; c < SCAN_CH; c += 224) cp_async16(dst + c * 16, src + c * 16);
            CP_COMMIT();
        }
    }

    __syncthreads();  // s_tg/s_mask visible to all

    // t=0 init: sa[j] = X0[L-1,j] / X0[L-1,0]; P0 = log(X0[L-1,0])
    float P0 = 0.f, tgtE_reg = 0.f;
    if (wid == 0) {
        float v0 = (lane < LBL) ? __bfloat162float(Xb[(LBL - 1) * LBL + lane]) : 1.f;
        float v1 = (lane + 32 < LBL) ? __bfloat162float(Xb[(LBL - 1) * LBL + lane + 32]) : 1.f;
        float vr = __shfl_sync(0xffffffffu, v0, 0);
        float inv = __fdividef(1.f, vr);
        if (lane < LBL)      sa[lane]      = v0 * inv;
        if (lane + 32 < LBL) sa[lane + 32] = v1 * inv;
        P0 = __logf(vr);
    }
    if (tid == 255)
        tgtE_reg = __logf(__bfloat162float(Xb[(LBL - 1) * LBL + s_tg[0]]));
    // (sa visibility guaranteed by the first loop barrier)

#pragma unroll 1
    for (int t = 1; t < TT; t++) {
        if (wid > 0) {
            const int tf = (t + 5 < TT) ? (t + 5) : (TT - 1);
            const char* src = (const char*)(Xb + (size_t)tf * ESTR);
            uint32_t dst = smem_u32(buf[(t + 5) % 6]);
            const int c0 = tid - 32;
            for (int c = c0; c < SCAN_CH; c += 224) cp_async16(dst + c * 16, src + c * 16);
            CP_COMMIT();
            CP_WAIT(5);
        }
        __syncthreads();  // (1) buf[t%6] ready; sa from previous step visible

        const __nv_bfloat16* Xc = buf[t % 6];

        float s = 0.f, s2 = 0.f;
        if (j < LBL) {
#pragma unroll
            for (int it = 0; it < 13; it++) {
                int i = g + 4 * it;
                if (i < LBL) {
                    float v = sa[i] * __bfloat162float(Xc[i * LBL + j]);
                    if (it & 1) s2 += v; else s += v;
                }
            }
            s += s2;
        }
        red[tid] = s;
        if (tid == 255)
            tgtE_reg += __logf(__bfloat162float(Xc[s_tg[t - 1] * LBL + s_tg[t]]));
        __syncthreads();  // (2) partials ready

        if (wid == 0) {
            const float m = s_mask[t];
            float tot0 = red[lane] + red[lane + 64] + red[lane + 128] + red[lane + 192];
            float tot1 = red[lane + 32] + red[lane + 96] + red[lane + 160] + red[lane + 224];
            float tr = __shfl_sync(0xffffffffu, tot0, 0);
            if (m == 1.0f) {
                float inv = __fdividef(1.f, tr);
                if (lane < LBL)      sa[lane]      = tot0 * inv;
                if (lane + 32 < LBL) sa[lane + 32] = tot1 * inv;
                P0 += __logf(tr);          // off critical path
            } else if (m != 0.0f) {
                float pj0 = (lane < LBL) ? (P0 + __logf(sa[lane])) : -1e30f;
                float pj1 = (lane + 32 < LBL) ? (P0 + __logf(sa[lane + 32])) : -1e30f;
                float pn0 = P0 + __logf(tot0);
                float pn1 = P0 + __logf(tot1);
                pj0 += (pn0 - pj0) * m;
                pj1 += (pn1 - pj1) * m;
                float nr = __shfl_sync(0xffffffffu, pj0, 0);
                if (lane < LBL)      sa[lane]      = __expf(pj0 - nr);
                if (lane + 32 < LBL) sa[lane + 32] = __expf(pj1 - nr);
                P0 = nr;
            }
            // m == 0: unchanged
        }
        // next iteration's barrier (1) protects sa
    }

    if (tid == 255) s_tgtE[0] = tgtE_reg;
    __syncthreads();

    if (wid == 0) {
        float sm = 0.f;
        if (lane < LBL)      sm += sa[lane];
        if (lane + 32 < LBL) sm += sa[lane + 32];
#pragma unroll
        for (int o = 16; o > 0; o >>= 1)
            sm += __shfl_xor_sync(0xffffffffu, sm, o);
        if (lane == 0) out[b] = P0 + __logf(sm) - s_tgtE[0];
    }
}

// ---------------------------------------------------------------------------
extern "C" void kernel_launch(void* const* d_in, const int* in_sizes, int n_in,
                              void* d_out, int out_size) {
    const float* input  = (const float*)d_in[0];
    const float* mask   = (const float*)d_in[1];
    const int*   target = (const int*)d_in[2];
    const float* sW     = (const float*)d_in[3];
    const float* sb     = (const float*)d_in[4];
    const float* tW     = (const float*)d_in[5];
    const float* tb     = (const float*)d_in[6];
    float* out = (float*)d_out;

    (void)in_sizes; (void)n_in; (void)out_size;

    prep_kernel<<<PREP_A_BLOCKS + PREP_W_BLOCKS, 256>>>(input, sW, sb, tW, tb);

    dim3 ggrid(NPAD / 128, MM / 128);  // (21, 128)
    gemm_exp_kernel<<<ggrid, 256>>>(mask);

    scan_kernel<<<BB, 256>>>(mask, target, out);
}